// round 9
// baseline (speedup 1.0000x reference)
#include <cuda_runtime.h>
#include <cuda_bf16.h>
#include <cstdint>
#include <cmath>

#define NN 8192
#define DD 512
#define NCLS 100
#define NTILE 64            // 8192/128 tiles per side
#define NTRI (NTILE * (NTILE + 1) / 2)   // 2080 upper-tri tiles

// ---------------------------------------------------------------------------
// Device globals
// ---------------------------------------------------------------------------
static __device__ __nv_bfloat16 g_hi[NN * DD];   // 8 MB
static __device__ __nv_bfloat16 g_lo[NN * DD];   // 8 MB
static __device__ int   g_lab[NN];
static __device__ float g_cnt[NN];               // (#same-label) - 1
static __device__ float g_ps[NN];                // sum of pos scores (raw)
static __device__ float g_ng[NN];                // sum of exp(neg scores)

// ---------------------------------------------------------------------------
// Baseline-ISA PTX helpers (no 'a'-features: works at target sm_103)
// ---------------------------------------------------------------------------
__device__ __forceinline__ uint32_t smem_u32(const void* p) {
    uint32_t a;
    asm("{ .reg .u64 t; cvta.to.shared.u64 t, %1; cvt.u32.u64 %0, t; }" : "=r"(a) : "l"(p));
    return a;
}

#define CP_ASYNC16(saddr, gaddr) \
    asm volatile("cp.async.cg.shared.global [%0], [%1], 16;" :: "r"(saddr), "l"(gaddr) : "memory")
#define CP_COMMIT() asm volatile("cp.async.commit_group;" ::: "memory")
#define CP_WAIT0()  asm volatile("cp.async.wait_group 0;" ::: "memory")
#define CP_WAIT1()  asm volatile("cp.async.wait_group 1;" ::: "memory")

#define LDSM4(r0, r1, r2, r3, addr) \
    asm volatile("ldmatrix.sync.aligned.m8n8.x4.shared.b16 {%0,%1,%2,%3}, [%4];" \
                 : "=r"(r0), "=r"(r1), "=r"(r2), "=r"(r3) : "r"(addr))

#define MMA16816(c, a0, a1, a2, a3, b0, b1) \
    asm volatile("mma.sync.aligned.m16n8k16.row.col.f32.bf16.bf16.f32 " \
                 "{%0,%1,%2,%3}, {%4,%5,%6,%7}, {%8,%9}, {%0,%1,%2,%3};" \
                 : "+f"((c)[0]), "+f"((c)[1]), "+f"((c)[2]), "+f"((c)[3]) \
                 : "r"(a0), "r"(a1), "r"(a2), "r"(a3), "r"(b0), "r"(b1))

// ---------------------------------------------------------------------------
// Small kernels
// ---------------------------------------------------------------------------
__global__ __launch_bounds__(256) void init_sums_kernel() {
    int i = blockIdx.x * 256 + threadIdx.x;
    if (i < NN) { g_ps[i] = 0.0f; g_ng[i] = 0.0f; }
}

// Detect int64 vs int32 labels, fill g_lab, build per-row same-label count.
__global__ __launch_bounds__(256) void label_kernel(const int* __restrict__ lraw) {
    __shared__ int any;
    __shared__ int hist[NCLS];
    int t = threadIdx.x;
    if (t == 0) any = 0;
    if (t < NCLS) hist[t] = 0;
    __syncthreads();
    int acc = 0;
    for (int w = 1 + 2 * t; w < NN; w += 512) acc |= lraw[w];
    if (acc) atomicOr(&any, 1);
    __syncthreads();
    bool is64 = (any == 0);
    if (is64) {
        const long long* l64 = (const long long*)lraw;
        for (int i = t; i < NN; i += 256) g_lab[i] = (int)l64[i];
    } else {
        for (int i = t; i < NN; i += 256) g_lab[i] = lraw[i];
    }
    __syncthreads();
    for (int i = t; i < NN; i += 256) atomicAdd(&hist[g_lab[i]], 1);
    __syncthreads();
    for (int i = t; i < NN; i += 256) g_cnt[i] = (float)(hist[g_lab[i]] - 1);
}

// Normalize each row, split into bf16 hi + lo.
__global__ __launch_bounds__(128) void prep_kernel(const float* __restrict__ reps) {
    int i = blockIdx.x;
    int t = threadIdx.x;
    const float4* row = (const float4*)(reps + (size_t)i * DD);
    float4 v = row[t];
    float ss = v.x * v.x + v.y * v.y + v.z * v.z + v.w * v.w;
    #pragma unroll
    for (int o = 16; o > 0; o >>= 1) ss += __shfl_down_sync(0xffffffffu, ss, o);
    __shared__ float ws[4];
    if ((t & 31) == 0) ws[t >> 5] = ss;
    __syncthreads();
    float tot = ws[0] + ws[1] + ws[2] + ws[3];
    float nrm = sqrtf(tot);
    float rn = (nrm > 1e-20f) ? (1.0f / nrm) : 0.0f;
    float x[4] = {v.x * rn, v.y * rn, v.z * rn, v.w * rn};
    __nv_bfloat16 h[4], l[4];
    #pragma unroll
    for (int q = 0; q < 4; q++) {
        h[q] = __float2bfloat16(x[q]);
        l[q] = __float2bfloat16(x[q] - __bfloat162float(h[q]));
    }
    size_t base = (size_t)i * DD + (size_t)t * 4;
    __nv_bfloat162* hp = (__nv_bfloat162*)(g_hi + base);
    __nv_bfloat162* lp = (__nv_bfloat162*)(g_lo + base);
    hp[0] = __nv_bfloat162{h[0], h[1]}; hp[1] = __nv_bfloat162{h[2], h[3]};
    lp[0] = __nv_bfloat162{l[0], l[1]}; lp[1] = __nv_bfloat162{l[2], l[3]};
}

// ---------------------------------------------------------------------------
// Fused HMMA Gram + contrastive row-sum epilogue.
// 1-D triangular grid (2080 CTAs), 128x128 tile each.  G = hi.hi+hi.lo+lo.hi.
// 8 warps (2x4): each warp 64x32 via m16n8k16.  KC=32, cp.async double buffer.
// __launch_bounds__(256,2) caps regs at 128 -> 2 CTA/SM (fixes occ=12.5%).
// Diagonal tiles skip the B loads (B region aliases A).
// ---------------------------------------------------------------------------
#define KC 32
#define ROWB 80                         // bytes per smem row (64 data + 16 pad)
#define TILEB (128 * ROWB)              // 10240 B per matrix
#define BUFB (4 * TILEB)                // Ahi, Alo, Bhi, Blo
#define DSMEM_BYTES (2 * BUFB)          // 81920

__global__ __launch_bounds__(256, 2) void gram_kernel() {
    // Triangular index -> (by, bx), bx >= by.
    int tidx = blockIdx.x;
    int by = (int)((2.0 * NTILE + 1.0 - sqrt((2.0 * NTILE + 1.0) * (2.0 * NTILE + 1.0)
                                             - 8.0 * (double)tidx)) * 0.5);
    // guard rounding
    while ((by + 1) * (2 * NTILE - by) / 2 <= tidx) by++;
    while (by * (2 * NTILE - by + 1) / 2 > tidx) by--;
    int bx = by + (tidx - by * (2 * NTILE - by + 1) / 2);

    extern __shared__ char dsmem[];
    __shared__ float s_rps[128], s_rng[128], s_cps[128], s_cng[128];
    __shared__ int s_labA[128], s_labB[128];

    int tid = threadIdx.x;
    int lane = tid & 31;
    int wid = tid >> 5;
    int warp_m = wid >> 2;       // 0..1
    int warp_n = wid & 3;        // 0..3
    bool diag = (bx == by);
    int bm = by << 7, bn = bx << 7;

    uint32_t sbase = smem_u32(dsmem);

    if (tid < 128) {
        s_labA[tid] = g_lab[bm + tid];
        s_labB[tid] = g_lab[bn + tid];
        s_rps[tid] = 0.0f; s_rng[tid] = 0.0f;
        s_cps[tid] = 0.0f; s_cng[tid] = 0.0f;
    }

    // ---- async tile loader (chunk c -> buffer b) ----
    // Matrices: 0=Ahi 1=Alo 2=Bhi 3=Blo; diag tiles load only A (B aliases A).
    int nmat = diag ? 2 : 4;
    auto load_chunk = [&](int c, int b) {
        int k0 = c * KC;
        uint32_t sb = sbase + b * BUFB;
        for (int m = 0; m < nmat; m++) {
            const __nv_bfloat16* gsrc = (m & 1) ? g_lo : g_hi;
            int rbase = (m < 2) ? bm : bn;
            uint32_t smat = sb + m * TILEB;
            #pragma unroll
            for (int it = 0; it < 2; it++) {
                int u = tid + it * 256;       // 0..511
                int row = u >> 2;             // 0..127
                int seg = u & 3;              // 16B segments
                const void* g = gsrc + (size_t)(rbase + row) * DD + k0 + seg * 8;
                uint32_t s = smat + row * ROWB + seg * 16;
                CP_ASYNC16(s, g);
            }
        }
    };

    float acc[4][4][4];
    #pragma unroll
    for (int mt = 0; mt < 4; mt++)
        #pragma unroll
        for (int nt = 0; nt < 4; nt++)
            #pragma unroll
            for (int e = 0; e < 4; e++) acc[mt][nt][e] = 0.0f;

    load_chunk(0, 0);
    CP_COMMIT();

    uint32_t boffB = diag ? 0u : (uint32_t)(2 * TILEB);   // B aliases A on diag

    const int NCHUNK = DD / KC;  // 16
    for (int c = 0; c < NCHUNK; c++) {
        if (c < NCHUNK - 1) { load_chunk(c + 1, (c + 1) & 1); CP_COMMIT(); CP_WAIT1(); }
        else                { CP_WAIT0(); }
        __syncthreads();

        uint32_t ab  = sbase + (c & 1) * BUFB;          // Ahi
        uint32_t alb = ab + TILEB;                      // Alo
        uint32_t bb  = ab + boffB;                      // Bhi
        uint32_t blb = bb + TILEB;                      // Blo

        #pragma unroll
        for (int ks = 0; ks < 2; ks++) {
            int k0 = ks * 16;
            // B fragments: x4 covers two n-tiles (16 n-rows) at k0/k0+8
            uint32_t bh[8], bl[8];
            #pragma unroll
            for (int p = 0; p < 2; p++) {
                int nrow = warp_n * 32 + p * 16 + (lane & 7) + ((lane >> 4) << 3);
                int koff = k0 + ((lane >> 3) & 1) * 8;
                uint32_t boff = nrow * ROWB + koff * 2;
                LDSM4(bh[p*4+0], bh[p*4+1], bh[p*4+2], bh[p*4+3], bb + boff);
                LDSM4(bl[p*4+0], bl[p*4+1], bl[p*4+2], bl[p*4+3], blb + boff);
            }
            #pragma unroll
            for (int mt = 0; mt < 4; mt++) {
                int arow = warp_m * 64 + mt * 16 + (lane & 15);
                int koff = k0 + (lane >> 4) * 8;
                uint32_t aoff = arow * ROWB + koff * 2;
                uint32_t ah0, ah1, ah2, ah3, al0, al1, al2, al3;
                LDSM4(ah0, ah1, ah2, ah3, ab + aoff);
                LDSM4(al0, al1, al2, al3, alb + aoff);
                #pragma unroll
                for (int nt = 0; nt < 4; nt++) {
                    int bi = (nt >> 1) * 4 + (nt & 1) * 2;
                    MMA16816(acc[mt][nt], ah0, ah1, ah2, ah3, bh[bi], bh[bi+1]);
                    MMA16816(acc[mt][nt], ah0, ah1, ah2, ah3, bl[bi], bl[bi+1]);
                    MMA16816(acc[mt][nt], al0, al1, al2, al3, bh[bi], bh[bi+1]);
                }
            }
        }
        __syncthreads();
    }

    // ---------------- fused contrastive epilogue ----------------
    int qid = lane >> 2;        // 0..7
    int cpos = lane & 3;        // 0..3
    float rowPS[4][2], rowNG[4][2], colPS[4][2], colNG[4][2];
    #pragma unroll
    for (int a = 0; a < 4; a++)
        #pragma unroll
        for (int h = 0; h < 2; h++) {
            rowPS[a][h] = 0.0f; rowNG[a][h] = 0.0f;
            colPS[a][h] = 0.0f; colNG[a][h] = 0.0f;
        }

    #pragma unroll
    for (int mt = 0; mt < 4; mt++) {
        #pragma unroll
        for (int half = 0; half < 2; half++) {
            int il = warp_m * 64 + mt * 16 + qid + half * 8;
            int li = s_labA[il];
            int gi = bm + il;
            #pragma unroll
            for (int nt = 0; nt < 4; nt++) {
                #pragma unroll
                for (int b = 0; b < 2; b++) {
                    int jl = warp_n * 32 + nt * 8 + cpos * 2 + b;
                    float g = acc[mt][nt][half * 2 + b];
                    float s = fmaf(g, 5.0f, 5.0f + 1e-7f);
                    bool same = (s_labB[jl] == li);
                    bool isd = (gi == bn + jl);
                    float pc = (same && !isd) ? s : 0.0f;
                    float e  = same ? 0.0f : __expf(s);
                    rowPS[mt][half] += pc;  rowNG[mt][half] += e;
                    colPS[nt][b]    += pc;  colNG[nt][b]    += e;
                }
            }
        }
    }
    #pragma unroll
    for (int mt = 0; mt < 4; mt++)
        #pragma unroll
        for (int half = 0; half < 2; half++) {
            int il = warp_m * 64 + mt * 16 + qid + half * 8;
            atomicAdd(&s_rps[il], rowPS[mt][half]);
            atomicAdd(&s_rng[il], rowNG[mt][half]);
        }
    if (!diag) {
        #pragma unroll
        for (int nt = 0; nt < 4; nt++)
            #pragma unroll
            for (int b = 0; b < 2; b++) {
                int jl = warp_n * 32 + nt * 8 + cpos * 2 + b;
                atomicAdd(&s_cps[jl], colPS[nt][b]);
                atomicAdd(&s_cng[jl], colNG[nt][b]);
            }
    }
    __syncthreads();
    if (tid < 128) {
        atomicAdd(&g_ps[bm + tid], s_rps[tid]);
        atomicAdd(&g_ng[bm + tid], s_rng[tid]);
        if (!diag) {
            atomicAdd(&g_ps[bn + tid], s_cps[tid]);
            atomicAdd(&g_ng[bn + tid], s_cng[tid]);
        }
    }
}

// ---------------------------------------------------------------------------
// Final: loss_i = -ps/(cnt+eps) + log(ng+eps); masked mean of loss>0.
// (Global max-shift cancels analytically to ~1e-9 absolute — omitted.)
// ---------------------------------------------------------------------------
__global__ __launch_bounds__(256) void loss_kernel(float* __restrict__ out) {
    int t = threadIdx.x;
    float s = 0.0f, c = 0.0f;
    for (int i = t; i < NN; i += 256) {
        float l = -g_ps[i] / (g_cnt[i] + 1e-8f) + logf(g_ng[i] + 1e-8f);
        if (l > 0.0f) { s += l; c += 1.0f; }
    }
    #pragma unroll
    for (int o = 16; o > 0; o >>= 1) {
        s += __shfl_down_sync(0xffffffffu, s, o);
        c += __shfl_down_sync(0xffffffffu, c, o);
    }
    __shared__ float ssum[8], scnt[8];
    if ((t & 31) == 0) { ssum[t >> 5] = s; scnt[t >> 5] = c; }
    __syncthreads();
    if (t == 0) {
        float S = 0.0f, C = 0.0f;
        #pragma unroll
        for (int w = 0; w < 8; w++) { S += ssum[w]; C += scnt[w]; }
        out[0] = S / (C + 1e-8f);
    }
}

// ---------------------------------------------------------------------------
extern "C" void kernel_launch(void* const* d_in, const int* in_sizes, int n_in,
                              void* d_out, int out_size) {
    (void)in_sizes; (void)n_in; (void)out_size;
    const float* reps = (const float*)d_in[0];
    const int*   lraw = (const int*)d_in[1];
    float*       out  = (float*)d_out;

    cudaFuncSetAttribute(gram_kernel, cudaFuncAttributeMaxDynamicSharedMemorySize,
                         DSMEM_BYTES);

    init_sums_kernel<<<(NN + 255) / 256, 256>>>();
    label_kernel<<<1, 256>>>(lraw);
    prep_kernel<<<NN, 128>>>(reps);
    gram_kernel<<<NTRI, 256, DSMEM_BYTES>>>();
    loss_kernel<<<1, 256>>>(out);
}

// round 10
// speedup vs baseline: 1.0586x; 1.0586x over previous
#include <cuda_runtime.h>
#include <cuda_bf16.h>
#include <cstdint>
#include <cmath>

#define NN 8192
#define DD 512
#define NCLS 100
#define NTILE 64                         // 8192/128 tiles per side
#define NTRI (NTILE * (NTILE + 1) / 2)   // 2080 upper-tri tiles

// ---------------------------------------------------------------------------
// Device globals
// ---------------------------------------------------------------------------
static __device__ __nv_bfloat16 g_hi[NN * DD];   // 8 MB
static __device__ __nv_bfloat16 g_lo[NN * DD];   // 8 MB
static __device__ int   g_lab[NN];
static __device__ float g_cnt[NN];               // (#same-label) - 1
static __device__ float g_ps[NN];                // sum of pos scores (raw)
static __device__ float g_ng[NN];                // sum of exp(neg scores)

// ---------------------------------------------------------------------------
// Baseline-ISA PTX helpers (no 'a'-features: works at target sm_103)
// ---------------------------------------------------------------------------
__device__ __forceinline__ uint32_t smem_u32(const void* p) {
    uint32_t a;
    asm("{ .reg .u64 t; cvta.to.shared.u64 t, %1; cvt.u32.u64 %0, t; }" : "=r"(a) : "l"(p));
    return a;
}

#define CP_ASYNC16(saddr, gaddr) \
    asm volatile("cp.async.cg.shared.global [%0], [%1], 16;" :: "r"(saddr), "l"(gaddr) : "memory")
#define CP_COMMIT() asm volatile("cp.async.commit_group;" ::: "memory")
#define CP_WAIT0()  asm volatile("cp.async.wait_group 0;" ::: "memory")
#define CP_WAIT1()  asm volatile("cp.async.wait_group 1;" ::: "memory")

#define LDSM4(r0, r1, r2, r3, addr) \
    asm volatile("ldmatrix.sync.aligned.m8n8.x4.shared.b16 {%0,%1,%2,%3}, [%4];" \
                 : "=r"(r0), "=r"(r1), "=r"(r2), "=r"(r3) : "r"(addr))

#define MMA16816(c, a0, a1, a2, a3, b0, b1) \
    asm volatile("mma.sync.aligned.m16n8k16.row.col.f32.bf16.bf16.f32 " \
                 "{%0,%1,%2,%3}, {%4,%5,%6,%7}, {%8,%9}, {%0,%1,%2,%3};" \
                 : "+f"((c)[0]), "+f"((c)[1]), "+f"((c)[2]), "+f"((c)[3]) \
                 : "r"(a0), "r"(a1), "r"(a2), "r"(a3), "r"(b0), "r"(b1))

// ---------------------------------------------------------------------------
// Small kernels
// ---------------------------------------------------------------------------
__global__ __launch_bounds__(256) void init_sums_kernel() {
    int i = blockIdx.x * 256 + threadIdx.x;
    if (i < NN) { g_ps[i] = 0.0f; g_ng[i] = 0.0f; }
}

// Detect int64 vs int32 labels, fill g_lab, build per-row same-label count.
__global__ __launch_bounds__(256) void label_kernel(const int* __restrict__ lraw) {
    __shared__ int any;
    __shared__ int hist[NCLS];
    int t = threadIdx.x;
    if (t == 0) any = 0;
    if (t < NCLS) hist[t] = 0;
    __syncthreads();
    int acc = 0;
    for (int w = 1 + 2 * t; w < NN; w += 512) acc |= lraw[w];
    if (acc) atomicOr(&any, 1);
    __syncthreads();
    bool is64 = (any == 0);
    if (is64) {
        const long long* l64 = (const long long*)lraw;
        for (int i = t; i < NN; i += 256) g_lab[i] = (int)l64[i];
    } else {
        for (int i = t; i < NN; i += 256) g_lab[i] = lraw[i];
    }
    __syncthreads();
    for (int i = t; i < NN; i += 256) atomicAdd(&hist[g_lab[i]], 1);
    __syncthreads();
    for (int i = t; i < NN; i += 256) g_cnt[i] = (float)(hist[g_lab[i]] - 1);
}

// Normalize each row, split into bf16 hi + lo.
__global__ __launch_bounds__(128) void prep_kernel(const float* __restrict__ reps) {
    int i = blockIdx.x;
    int t = threadIdx.x;
    const float4* row = (const float4*)(reps + (size_t)i * DD);
    float4 v = row[t];
    float ss = v.x * v.x + v.y * v.y + v.z * v.z + v.w * v.w;
    #pragma unroll
    for (int o = 16; o > 0; o >>= 1) ss += __shfl_down_sync(0xffffffffu, ss, o);
    __shared__ float ws[4];
    if ((t & 31) == 0) ws[t >> 5] = ss;
    __syncthreads();
    float tot = ws[0] + ws[1] + ws[2] + ws[3];
    float nrm = sqrtf(tot);
    float rn = (nrm > 1e-20f) ? (1.0f / nrm) : 0.0f;
    float x[4] = {v.x * rn, v.y * rn, v.z * rn, v.w * rn};
    __nv_bfloat16 h[4], l[4];
    #pragma unroll
    for (int q = 0; q < 4; q++) {
        h[q] = __float2bfloat16(x[q]);
        l[q] = __float2bfloat16(x[q] - __bfloat162float(h[q]));
    }
    size_t base = (size_t)i * DD + (size_t)t * 4;
    __nv_bfloat162* hp = (__nv_bfloat162*)(g_hi + base);
    __nv_bfloat162* lp = (__nv_bfloat162*)(g_lo + base);
    hp[0] = __nv_bfloat162{h[0], h[1]}; hp[1] = __nv_bfloat162{h[2], h[3]};
    lp[0] = __nv_bfloat162{l[0], l[1]}; lp[1] = __nv_bfloat162{l[2], l[3]};
}

// ---------------------------------------------------------------------------
// Fused HMMA Gram + contrastive row-sum epilogue.
// 1-D triangular grid (2080 CTAs), 128x128 tile each.  G = hi.hi+hi.lo+lo.hi.
// 512 threads, 16 warps (4x4): each warp 32x32 via m16n8k16 -> acc only 32
// regs/thread, so no spills and no register cap needed (R9's 128-reg cap
// spilled: L1 25.6->36%, dur regressed).  KC=32, cp.async double buffer.
// Diagonal tiles skip the B loads (B region aliases A).
// ---------------------------------------------------------------------------
#define KC 32
#define ROWB 80                         // bytes per smem row (64 data + 16 pad)
#define TILEB (128 * ROWB)              // 10240 B per matrix
#define BUFB (4 * TILEB)                // Ahi, Alo, Bhi, Blo
#define DSMEM_BYTES (2 * BUFB)          // 81920

__global__ __launch_bounds__(512) void gram_kernel() {
    // Triangular index -> (by, bx), bx >= by.
    int tidx = blockIdx.x;
    int by = (int)((2.0 * NTILE + 1.0 - sqrt((2.0 * NTILE + 1.0) * (2.0 * NTILE + 1.0)
                                             - 8.0 * (double)tidx)) * 0.5);
    while ((by + 1) * (2 * NTILE - by) / 2 <= tidx) by++;
    while (by * (2 * NTILE - by + 1) / 2 > tidx) by--;
    int bx = by + (tidx - by * (2 * NTILE - by + 1) / 2);

    extern __shared__ char dsmem[];
    __shared__ float s_rps[128], s_rng[128], s_cps[128], s_cng[128];
    __shared__ int s_labA[128], s_labB[128];

    int tid = threadIdx.x;
    int lane = tid & 31;
    int wid = tid >> 5;          // 0..15
    int warp_m = wid >> 2;       // 0..3
    int warp_n = wid & 3;        // 0..3
    bool diag = (bx == by);
    int bm = by << 7, bn = bx << 7;

    uint32_t sbase = smem_u32(dsmem);

    if (tid < 128) {
        s_labA[tid] = g_lab[bm + tid];
        s_labB[tid] = g_lab[bn + tid];
        s_rps[tid] = 0.0f; s_rng[tid] = 0.0f;
        s_cps[tid] = 0.0f; s_cng[tid] = 0.0f;
    }

    // ---- async tile loader (chunk c -> buffer b) ----
    // 512 threads: exactly one 16B cp.async per thread per matrix.
    // Matrices: 0=Ahi 1=Alo 2=Bhi 3=Blo; diag tiles load only A (B aliases A).
    int nmat = diag ? 2 : 4;
    int lrow = tid >> 2;          // 0..127
    int lseg = tid & 3;           // 16B segment
    auto load_chunk = [&](int c, int b) {
        int k0 = c * KC;
        uint32_t sb = sbase + b * BUFB + lrow * ROWB + lseg * 16;
        size_t goA = (size_t)(bm + lrow) * DD + k0 + lseg * 8;
        size_t goB = (size_t)(bn + lrow) * DD + k0 + lseg * 8;
        CP_ASYNC16(sb + 0 * TILEB, g_hi + goA);
        CP_ASYNC16(sb + 1 * TILEB, g_lo + goA);
        if (nmat == 4) {
            CP_ASYNC16(sb + 2 * TILEB, g_hi + goB);
            CP_ASYNC16(sb + 3 * TILEB, g_lo + goB);
        }
    };

    float acc[2][4][4];
    #pragma unroll
    for (int mt = 0; mt < 2; mt++)
        #pragma unroll
        for (int nt = 0; nt < 4; nt++)
            #pragma unroll
            for (int e = 0; e < 4; e++) acc[mt][nt][e] = 0.0f;

    load_chunk(0, 0);
    CP_COMMIT();

    uint32_t boffB = diag ? 0u : (uint32_t)(2 * TILEB);   // B aliases A on diag

    const int NCHUNK = DD / KC;  // 16
    for (int c = 0; c < NCHUNK; c++) {
        if (c < NCHUNK - 1) { load_chunk(c + 1, (c + 1) & 1); CP_COMMIT(); CP_WAIT1(); }
        else                { CP_WAIT0(); }
        __syncthreads();

        uint32_t ab  = sbase + (c & 1) * BUFB;          // Ahi
        uint32_t alb = ab + TILEB;                      // Alo
        uint32_t bb  = ab + boffB;                      // Bhi
        uint32_t blb = bb + TILEB;                      // Blo

        #pragma unroll
        for (int ks = 0; ks < 2; ks++) {
            int k0 = ks * 16;
            // B fragments: two x4 loads cover 32 n-rows at k0/k0+8
            uint32_t bh[8], bl[8];
            #pragma unroll
            for (int p = 0; p < 2; p++) {
                int nrow = warp_n * 32 + p * 16 + (lane & 7) + ((lane >> 4) << 3);
                int koff = k0 + ((lane >> 3) & 1) * 8;
                uint32_t boff = nrow * ROWB + koff * 2;
                LDSM4(bh[p*4+0], bh[p*4+1], bh[p*4+2], bh[p*4+3], bb + boff);
                LDSM4(bl[p*4+0], bl[p*4+1], bl[p*4+2], bl[p*4+3], blb + boff);
            }
            #pragma unroll
            for (int mt = 0; mt < 2; mt++) {
                int arow = warp_m * 32 + mt * 16 + (lane & 15);
                int koff = k0 + (lane >> 4) * 8;
                uint32_t aoff = arow * ROWB + koff * 2;
                uint32_t ah0, ah1, ah2, ah3, al0, al1, al2, al3;
                LDSM4(ah0, ah1, ah2, ah3, ab + aoff);
                LDSM4(al0, al1, al2, al3, alb + aoff);
                #pragma unroll
                for (int nt = 0; nt < 4; nt++) {
                    int bi = (nt >> 1) * 4 + (nt & 1) * 2;
                    MMA16816(acc[mt][nt], ah0, ah1, ah2, ah3, bh[bi], bh[bi+1]);
                    MMA16816(acc[mt][nt], ah0, ah1, ah2, ah3, bl[bi], bl[bi+1]);
                    MMA16816(acc[mt][nt], al0, al1, al2, al3, bh[bi], bh[bi+1]);
                }
            }
        }
        __syncthreads();
    }

    // ---------------- fused contrastive epilogue ----------------
    int qid = lane >> 2;        // 0..7
    int cpos = lane & 3;        // 0..3
    float rowPS[2][2], rowNG[2][2], colPS[4][2], colNG[4][2];
    #pragma unroll
    for (int a = 0; a < 2; a++)
        #pragma unroll
        for (int h = 0; h < 2; h++) { rowPS[a][h] = 0.0f; rowNG[a][h] = 0.0f; }
    #pragma unroll
    for (int a = 0; a < 4; a++)
        #pragma unroll
        for (int h = 0; h < 2; h++) { colPS[a][h] = 0.0f; colNG[a][h] = 0.0f; }

    #pragma unroll
    for (int mt = 0; mt < 2; mt++) {
        #pragma unroll
        for (int half = 0; half < 2; half++) {
            int il = warp_m * 32 + mt * 16 + qid + half * 8;
            int li = s_labA[il];
            int gi = bm + il;
            #pragma unroll
            for (int nt = 0; nt < 4; nt++) {
                #pragma unroll
                for (int b = 0; b < 2; b++) {
                    int jl = warp_n * 32 + nt * 8 + cpos * 2 + b;
                    float g = acc[mt][nt][half * 2 + b];
                    float s = fmaf(g, 5.0f, 5.0f + 1e-7f);
                    bool same = (s_labB[jl] == li);
                    bool isd = (gi == bn + jl);
                    float pc = (same && !isd) ? s : 0.0f;
                    float e  = same ? 0.0f : __expf(s);
                    rowPS[mt][half] += pc;  rowNG[mt][half] += e;
                    colPS[nt][b]    += pc;  colNG[nt][b]    += e;
                }
            }
        }
    }
    #pragma unroll
    for (int mt = 0; mt < 2; mt++)
        #pragma unroll
        for (int half = 0; half < 2; half++) {
            int il = warp_m * 32 + mt * 16 + qid + half * 8;
            atomicAdd(&s_rps[il], rowPS[mt][half]);
            atomicAdd(&s_rng[il], rowNG[mt][half]);
        }
    if (!diag) {
        #pragma unroll
        for (int nt = 0; nt < 4; nt++)
            #pragma unroll
            for (int b = 0; b < 2; b++) {
                int jl = warp_n * 32 + nt * 8 + cpos * 2 + b;
                atomicAdd(&s_cps[jl], colPS[nt][b]);
                atomicAdd(&s_cng[jl], colNG[nt][b]);
            }
    }
    __syncthreads();
    if (tid < 128) {
        atomicAdd(&g_ps[bm + tid], s_rps[tid]);
        atomicAdd(&g_ng[bm + tid], s_rng[tid]);
        if (!diag) {
            atomicAdd(&g_ps[bn + tid], s_cps[tid]);
            atomicAdd(&g_ng[bn + tid], s_cng[tid]);
        }
    }
}

// ---------------------------------------------------------------------------
// Final: loss_i = -ps/(cnt+eps) + log(ng+eps); masked mean of loss>0.
// (Global max-shift cancels analytically to ~1e-9 absolute — omitted.)
// ---------------------------------------------------------------------------
__global__ __launch_bounds__(256) void loss_kernel(float* __restrict__ out) {
    int t = threadIdx.x;
    float s = 0.0f, c = 0.0f;
    for (int i = t; i < NN; i += 256) {
        float l = -g_ps[i] / (g_cnt[i] + 1e-8f) + logf(g_ng[i] + 1e-8f);
        if (l > 0.0f) { s += l; c += 1.0f; }
    }
    #pragma unroll
    for (int o = 16; o > 0; o >>= 1) {
        s += __shfl_down_sync(0xffffffffu, s, o);
        c += __shfl_down_sync(0xffffffffu, c, o);
    }
    __shared__ float ssum[8], scnt[8];
    if ((t & 31) == 0) { ssum[t >> 5] = s; scnt[t >> 5] = c; }
    __syncthreads();
    if (t == 0) {
        float S = 0.0f, C = 0.0f;
        #pragma unroll
        for (int w = 0; w < 8; w++) { S += ssum[w]; C += scnt[w]; }
        out[0] = S / (C + 1e-8f);
    }
}

// ---------------------------------------------------------------------------
extern "C" void kernel_launch(void* const* d_in, const int* in_sizes, int n_in,
                              void* d_out, int out_size) {
    (void)in_sizes; (void)n_in; (void)out_size;
    const float* reps = (const float*)d_in[0];
    const int*   lraw = (const int*)d_in[1];
    float*       out  = (float*)d_out;

    cudaFuncSetAttribute(gram_kernel, cudaFuncAttributeMaxDynamicSharedMemorySize,
                         DSMEM_BYTES);

    init_sums_kernel<<<(NN + 255) / 256, 256>>>();
    label_kernel<<<1, 256>>>(lraw);
    prep_kernel<<<NN, 128>>>(reps);
    gram_kernel<<<NTRI, 512, DSMEM_BYTES>>>();
    loss_kernel<<<1, 256>>>(out);
}

// round 12
// speedup vs baseline: 1.0591x; 1.0005x over previous
#include <cuda_runtime.h>
#include <cuda_bf16.h>
#include <cstdint>
#include <cmath>

#define NN 8192
#define DD 512
#define NCLS 100
#define NTILE 64                         // 8192/128 tiles per side
#define NTRI (NTILE * (NTILE + 1) / 2)   // 2080 upper-tri tiles

// ---------------------------------------------------------------------------
// Device globals
// ---------------------------------------------------------------------------
static __device__ __nv_bfloat16 g_hi[NN * DD];   // 8 MB
static __device__ __nv_bfloat16 g_lo[NN * DD];   // 8 MB
static __device__ int   g_lab[NN];
static __device__ float g_cnt[NN];               // (#same-label) - 1
static __device__ float g_ps[NN];                // sum of pos scores (raw)
static __device__ float g_ng[NN];                // sum of exp(neg scores)

// ---------------------------------------------------------------------------
// Baseline-ISA PTX helpers (no 'a'-features: works at target sm_103)
// ---------------------------------------------------------------------------
__device__ __forceinline__ uint32_t smem_u32(const void* p) {
    uint32_t a;
    asm("{ .reg .u64 t; cvta.to.shared.u64 t, %1; cvt.u32.u64 %0, t; }" : "=r"(a) : "l"(p));
    return a;
}

#define CP_ASYNC16(saddr, gaddr) \
    asm volatile("cp.async.cg.shared.global [%0], [%1], 16;" :: "r"(saddr), "l"(gaddr) : "memory")
#define CP_COMMIT() asm volatile("cp.async.commit_group;" ::: "memory")
#define CP_WAIT0()  asm volatile("cp.async.wait_group 0;" ::: "memory")
#define CP_WAIT1()  asm volatile("cp.async.wait_group 1;" ::: "memory")

#define LDSM4(r0, r1, r2, r3, addr) \
    asm volatile("ldmatrix.sync.aligned.m8n8.x4.shared.b16 {%0,%1,%2,%3}, [%4];" \
                 : "=r"(r0), "=r"(r1), "=r"(r2), "=r"(r3) : "r"(addr))

#define MMA16816(c, a0, a1, a2, a3, b0, b1) \
    asm volatile("mma.sync.aligned.m16n8k16.row.col.f32.bf16.bf16.f32 " \
                 "{%0,%1,%2,%3}, {%4,%5,%6,%7}, {%8,%9}, {%0,%1,%2,%3};" \
                 : "+f"((c)[0]), "+f"((c)[1]), "+f"((c)[2]), "+f"((c)[3]) \
                 : "r"(a0), "r"(a1), "r"(a2), "r"(a3), "r"(b0), "r"(b1))

// ---------------------------------------------------------------------------
// Small kernels
// ---------------------------------------------------------------------------
__global__ __launch_bounds__(256) void init_sums_kernel() {
    int i = blockIdx.x * 256 + threadIdx.x;
    if (i < NN) { g_ps[i] = 0.0f; g_ng[i] = 0.0f; }
}

// Detect int64 vs int32 labels, fill g_lab, build per-row same-label count.
__global__ __launch_bounds__(256) void label_kernel(const int* __restrict__ lraw) {
    __shared__ int any;
    __shared__ int hist[NCLS];
    int t = threadIdx.x;
    if (t == 0) any = 0;
    if (t < NCLS) hist[t] = 0;
    __syncthreads();
    int acc = 0;
    for (int w = 1 + 2 * t; w < NN; w += 512) acc |= lraw[w];
    if (acc) atomicOr(&any, 1);
    __syncthreads();
    bool is64 = (any == 0);
    if (is64) {
        const long long* l64 = (const long long*)lraw;
        for (int i = t; i < NN; i += 256) g_lab[i] = (int)l64[i];
    } else {
        for (int i = t; i < NN; i += 256) g_lab[i] = lraw[i];
    }
    __syncthreads();
    for (int i = t; i < NN; i += 256) atomicAdd(&hist[g_lab[i]], 1);
    __syncthreads();
    for (int i = t; i < NN; i += 256) g_cnt[i] = (float)(hist[g_lab[i]] - 1);
}

// Normalize each row, split into bf16 hi + lo.
__global__ __launch_bounds__(128) void prep_kernel(const float* __restrict__ reps) {
    int i = blockIdx.x;
    int t = threadIdx.x;
    const float4* row = (const float4*)(reps + (size_t)i * DD);
    float4 v = row[t];
    float ss = v.x * v.x + v.y * v.y + v.z * v.z + v.w * v.w;
    #pragma unroll
    for (int o = 16; o > 0; o >>= 1) ss += __shfl_down_sync(0xffffffffu, ss, o);
    __shared__ float ws[4];
    if ((t & 31) == 0) ws[t >> 5] = ss;
    __syncthreads();
    float tot = ws[0] + ws[1] + ws[2] + ws[3];
    float nrm = sqrtf(tot);
    float rn = (nrm > 1e-20f) ? (1.0f / nrm) : 0.0f;
    float x[4] = {v.x * rn, v.y * rn, v.z * rn, v.w * rn};
    __nv_bfloat16 h[4], l[4];
    #pragma unroll
    for (int q = 0; q < 4; q++) {
        h[q] = __float2bfloat16(x[q]);
        l[q] = __float2bfloat16(x[q] - __bfloat162float(h[q]));
    }
    size_t base = (size_t)i * DD + (size_t)t * 4;
    __nv_bfloat162* hp = (__nv_bfloat162*)(g_hi + base);
    __nv_bfloat162* lp = (__nv_bfloat162*)(g_lo + base);
    hp[0] = __nv_bfloat162{h[0], h[1]}; hp[1] = __nv_bfloat162{h[2], h[3]};
    lp[0] = __nv_bfloat162{l[0], l[1]}; lp[1] = __nv_bfloat162{l[2], l[3]};
}

// ---------------------------------------------------------------------------
// Fused HMMA Gram + contrastive row-sum epilogue.
// 1-D triangular grid (2080 CTAs), 128x128 tile each.  G = hi.hi+hi.lo+lo.hi.
// 512 threads, 16 warps (4x4), warp tile 32x32 (no spills, regs ~80).
// NEW (R11): 3-stage cp.async pipeline, ONE __syncthreads per chunk
// (R10 had 2 barriers/chunk + 1-chunk runway -> tensor duty 33%).
// Diagonal tiles skip the B loads (B region aliases A).
// ---------------------------------------------------------------------------
#define KC 32
#define ROWB 80                         // bytes per smem row (64 data + 16 pad)
#define TILEB (128 * ROWB)              // 10240 B per matrix
#define BUFB (4 * TILEB)                // Ahi, Alo, Bhi, Blo
#define NSTAGE 3
#define DSMEM_BYTES (NSTAGE * BUFB)     // 122880

__global__ __launch_bounds__(512) void gram_kernel() {
    // Triangular index -> (by, bx), bx >= by.
    int tidx = blockIdx.x;
    int by = (int)((2.0 * NTILE + 1.0 - sqrt((2.0 * NTILE + 1.0) * (2.0 * NTILE + 1.0)
                                             - 8.0 * (double)tidx)) * 0.5);
    while ((by + 1) * (2 * NTILE - by) / 2 <= tidx) by++;
    while (by * (2 * NTILE - by + 1) / 2 > tidx) by--;
    int bx = by + (tidx - by * (2 * NTILE - by + 1) / 2);

    extern __shared__ char dsmem[];
    __shared__ float s_rps[128], s_rng[128], s_cps[128], s_cng[128];
    __shared__ int s_labA[128], s_labB[128];

    int tid = threadIdx.x;
    int lane = tid & 31;
    int wid = tid >> 5;          // 0..15
    int warp_m = wid >> 2;       // 0..3
    int warp_n = wid & 3;        // 0..3
    bool diag = (bx == by);
    int bm = by << 7, bn = bx << 7;

    uint32_t sbase = smem_u32(dsmem);

    if (tid < 128) {
        s_labA[tid] = g_lab[bm + tid];
        s_labB[tid] = g_lab[bn + tid];
        s_rps[tid] = 0.0f; s_rng[tid] = 0.0f;
        s_cps[tid] = 0.0f; s_cng[tid] = 0.0f;
    }

    // ---- async tile loader (chunk c -> stage s) ----
    // 512 threads: exactly one 16B cp.async per thread per matrix.
    // Matrices: 0=Ahi 1=Alo 2=Bhi 3=Blo; diag tiles load only A (B aliases A).
    int nmat = diag ? 2 : 4;
    int lrow = tid >> 2;          // 0..127
    int lseg = tid & 3;           // 16B segment
    auto load_chunk = [&](int c, int s) {
        int k0 = c * KC;
        uint32_t sb = sbase + s * BUFB + lrow * ROWB + lseg * 16;
        size_t goA = (size_t)(bm + lrow) * DD + k0 + lseg * 8;
        size_t goB = (size_t)(bn + lrow) * DD + k0 + lseg * 8;
        CP_ASYNC16(sb + 0 * TILEB, g_hi + goA);
        CP_ASYNC16(sb + 1 * TILEB, g_lo + goA);
        if (nmat == 4) {
            CP_ASYNC16(sb + 2 * TILEB, g_hi + goB);
            CP_ASYNC16(sb + 3 * TILEB, g_lo + goB);
        }
    };

    float acc[2][4][4];
    #pragma unroll
    for (int mt = 0; mt < 2; mt++)
        #pragma unroll
        for (int nt = 0; nt < 4; nt++)
            #pragma unroll
            for (int e = 0; e < 4; e++) acc[mt][nt][e] = 0.0f;

    // Prologue: 2 chunks of runway.
    load_chunk(0, 0); CP_COMMIT();
    load_chunk(1, 1); CP_COMMIT();

    uint32_t boffB = diag ? 0u : (uint32_t)(2 * TILEB);   // B aliases A on diag

    const int NCHUNK = DD / KC;  // 16
    int stage = 0;
    for (int c = 0; c < NCHUNK; c++) {
        // Pending groups at this point: {c, c+1}.  Wait for chunk c only.
        if (c < NCHUNK - 1) CP_WAIT1(); else CP_WAIT0();
        __syncthreads();
        // Refill: chunk c+2 into stage (c+2)%3 = stage of chunk c-1, whose
        // readers all finished compute(c-1) before this barrier.
        if (c + 2 < NCHUNK) {
            int ns = stage + 2; if (ns >= NSTAGE) ns -= NSTAGE;
            load_chunk(c + 2, ns);
            CP_COMMIT();
        }

        uint32_t ab  = sbase + stage * BUFB;            // Ahi
        uint32_t alb = ab + TILEB;                      // Alo
        uint32_t bb  = ab + boffB;                      // Bhi
        uint32_t blb = bb + TILEB;                      // Blo

        #pragma unroll
        for (int ks = 0; ks < 2; ks++) {
            int k0 = ks * 16;
            // B fragments: two x4 loads cover 32 n-rows at k0/k0+8
            uint32_t bh[8], bl[8];
            #pragma unroll
            for (int p = 0; p < 2; p++) {
                int nrow = warp_n * 32 + p * 16 + (lane & 7) + ((lane >> 4) << 3);
                int koff = k0 + ((lane >> 3) & 1) * 8;
                uint32_t boff = nrow * ROWB + koff * 2;
                LDSM4(bh[p*4+0], bh[p*4+1], bh[p*4+2], bh[p*4+3], bb + boff);
                LDSM4(bl[p*4+0], bl[p*4+1], bl[p*4+2], bl[p*4+3], blb + boff);
            }
            #pragma unroll
            for (int mt = 0; mt < 2; mt++) {
                int arow = warp_m * 32 + mt * 16 + (lane & 15);
                int koff = k0 + (lane >> 4) * 8;
                uint32_t aoff = arow * ROWB + koff * 2;
                uint32_t ah0, ah1, ah2, ah3, al0, al1, al2, al3;
                LDSM4(ah0, ah1, ah2, ah3, ab + aoff);
                LDSM4(al0, al1, al2, al3, alb + aoff);
                #pragma unroll
                for (int nt = 0; nt < 4; nt++) {
                    int bi = (nt >> 1) * 4 + (nt & 1) * 2;
                    MMA16816(acc[mt][nt], ah0, ah1, ah2, ah3, bh[bi], bh[bi+1]);
                    MMA16816(acc[mt][nt], ah0, ah1, ah2, ah3, bl[bi], bl[bi+1]);
                    MMA16816(acc[mt][nt], al0, al1, al2, al3, bh[bi], bh[bi+1]);
                }
            }
        }
        stage++; if (stage >= NSTAGE) stage -= NSTAGE;
        // NOTE: no trailing barrier — next iteration's top barrier provides
        // the ordering needed before stage reuse (overwrite distance 2).
    }

    // ---------------- fused contrastive epilogue ----------------
    __syncthreads();   // protect s_* arrays (written pre-loop) / ensure all MMA reads done
    int qid = lane >> 2;        // 0..7
    int cpos = lane & 3;        // 0..3
    float rowPS[2][2], rowNG[2][2], colPS[4][2], colNG[4][2];
    #pragma unroll
    for (int a = 0; a < 2; a++)
        #pragma unroll
        for (int h = 0; h < 2; h++) { rowPS[a][h] = 0.0f; rowNG[a][h] = 0.0f; }
    #pragma unroll
    for (int a = 0; a < 4; a++)
        #pragma unroll
        for (int h = 0; h < 2; h++) { colPS[a][h] = 0.0f; colNG[a][h] = 0.0f; }

    #pragma unroll
    for (int mt = 0; mt < 2; mt++) {
        #pragma unroll
        for (int half = 0; half < 2; half++) {
            int il = warp_m * 32 + mt * 16 + qid + half * 8;
            int li = s_labA[il];
            int gi = bm + il;
            #pragma unroll
            for (int nt = 0; nt < 4; nt++) {
                #pragma unroll
                for (int b = 0; b < 2; b++) {
                    int jl = warp_n * 32 + nt * 8 + cpos * 2 + b;
                    float g = acc[mt][nt][half * 2 + b];
                    float s = fmaf(g, 5.0f, 5.0f + 1e-7f);
                    bool same = (s_labB[jl] == li);
                    bool isd = (gi == bn + jl);
                    float pc = (same && !isd) ? s : 0.0f;
                    float e  = same ? 0.0f : __expf(s);
                    rowPS[mt][half] += pc;  rowNG[mt][half] += e;
                    colPS[nt][b]    += pc;  colNG[nt][b]    += e;
                }
            }
        }
    }
    #pragma unroll
    for (int mt = 0; mt < 2; mt++)
        #pragma unroll
        for (int half = 0; half < 2; half++) {
            int il = warp_m * 32 + mt * 16 + qid + half * 8;
            atomicAdd(&s_rps[il], rowPS[mt][half]);
            atomicAdd(&s_rng[il], rowNG[mt][half]);
        }
    if (!diag) {
        #pragma unroll
        for (int nt = 0; nt < 4; nt++)
            #pragma unroll
            for (int b = 0; b < 2; b++) {
                int jl = warp_n * 32 + nt * 8 + cpos * 2 + b;
                atomicAdd(&s_cps[jl], colPS[nt][b]);
                atomicAdd(&s_cng[jl], colNG[nt][b]);
            }
    }
    __syncthreads();
    if (tid < 128) {
        atomicAdd(&g_ps[bm + tid], s_rps[tid]);
        atomicAdd(&g_ng[bm + tid], s_rng[tid]);
        if (!diag) {
            atomicAdd(&g_ps[bn + tid], s_cps[tid]);
            atomicAdd(&g_ng[bn + tid], s_cng[tid]);
        }
    }
}

// ---------------------------------------------------------------------------
// Final: loss_i = -ps/(cnt+eps) + log(ng+eps); masked mean of loss>0.
// (Global max-shift cancels analytically to ~1e-9 absolute — omitted.)
// ---------------------------------------------------------------------------
__global__ __launch_bounds__(256) void loss_kernel(float* __restrict__ out) {
    int t = threadIdx.x;
    float s = 0.0f, c = 0.0f;
    for (int i = t; i < NN; i += 256) {
        float l = -g_ps[i] / (g_cnt[i] + 1e-8f) + logf(g_ng[i] + 1e-8f);
        if (l > 0.0f) { s += l; c += 1.0f; }
    }
    #pragma unroll
    for (int o = 16; o > 0; o >>= 1) {
        s += __shfl_down_sync(0xffffffffu, s, o);
        c += __shfl_down_sync(0xffffffffu, c, o);
    }
    __shared__ float ssum[8], scnt[8];
    if ((t & 31) == 0) { ssum[t >> 5] = s; scnt[t >> 5] = c; }
    __syncthreads();
    if (t == 0) {
        float S = 0.0f, C = 0.0f;
        #pragma unroll
        for (int w = 0; w < 8; w++) { S += ssum[w]; C += scnt[w]; }
        out[0] = S / (C + 1e-8f);
    }
}

// ---------------------------------------------------------------------------
extern "C" void kernel_launch(void* const* d_in, const int* in_sizes, int n_in,
                              void* d_out, int out_size) {
    (void)in_sizes; (void)n_in; (void)out_size;
    const float* reps = (const float*)d_in[0];
    const int*   lraw = (const int*)d_in[1];
    float*       out  = (float*)d_out;

    cudaFuncSetAttribute(gram_kernel, cudaFuncAttributeMaxDynamicSharedMemorySize,
                         DSMEM_BYTES);

    init_sums_kernel<<<(NN + 255) / 256, 256>>>();
    label_kernel<<<1, 256>>>(lraw);
    prep_kernel<<<NN, 128>>>(reps);
    gram_kernel<<<NTRI, 512, DSMEM_BYTES>>>();
    loss_kernel<<<1, 256>>>(out);
}

// round 14
// speedup vs baseline: 2.4533x; 2.3164x over previous
#include <cuda_runtime.h>
#include <cuda_bf16.h>
#include <cstdint>
#include <cmath>

#define NN 8192
#define DD 512
#define NCLS 100
#define NTILE 64                         // 8192/128 tiles per side
#define NTRI (NTILE * (NTILE + 1) / 2)   // 2080 upper-tri tiles

// ---------------------------------------------------------------------------
// Device globals
// ---------------------------------------------------------------------------
static __device__ __nv_bfloat16 g_bf[NN * DD];   // 8 MB normalized bf16 reps
static __device__ int   g_lab[NN];
static __device__ float g_cnt[NN];               // (#same-label) - 1
static __device__ float g_ps[NN];                // sum of pos scores (raw)
static __device__ float g_ng[NN];                // sum of exp(neg scores)

// ---------------------------------------------------------------------------
// Baseline-ISA PTX helpers (no 'a'-features: works at target sm_103)
// ---------------------------------------------------------------------------
__device__ __forceinline__ uint32_t smem_u32(const void* p) {
    uint32_t a;
    asm("{ .reg .u64 t; cvta.to.shared.u64 t, %1; cvt.u32.u64 %0, t; }" : "=r"(a) : "l"(p));
    return a;
}

#define CP_ASYNC16(saddr, gaddr) \
    asm volatile("cp.async.cg.shared.global [%0], [%1], 16;" :: "r"(saddr), "l"(gaddr) : "memory")
#define CP_COMMIT() asm volatile("cp.async.commit_group;" ::: "memory")
#define CP_WAIT0()  asm volatile("cp.async.wait_group 0;" ::: "memory")
#define CP_WAIT1()  asm volatile("cp.async.wait_group 1;" ::: "memory")

#define LDSM4(r0, r1, r2, r3, addr) \
    asm volatile("ldmatrix.sync.aligned.m8n8.x4.shared.b16 {%0,%1,%2,%3}, [%4];" \
                 : "=r"(r0), "=r"(r1), "=r"(r2), "=r"(r3) : "r"(addr))

#define MMA16816(c, a0, a1, a2, a3, b0, b1) \
    asm volatile("mma.sync.aligned.m16n8k16.row.col.f32.bf16.bf16.f32 " \
                 "{%0,%1,%2,%3}, {%4,%5,%6,%7}, {%8,%9}, {%0,%1,%2,%3};" \
                 : "+f"((c)[0]), "+f"((c)[1]), "+f"((c)[2]), "+f"((c)[3]) \
                 : "r"(a0), "r"(a1), "r"(a2), "r"(a3), "r"(b0), "r"(b1))

// ---------------------------------------------------------------------------
// Small kernels
// ---------------------------------------------------------------------------
__global__ __launch_bounds__(256) void init_sums_kernel() {
    int i = blockIdx.x * 256 + threadIdx.x;
    if (i < NN) { g_ps[i] = 0.0f; g_ng[i] = 0.0f; }
}

// Detect int64 vs int32 labels, fill g_lab, build per-row same-label count.
__global__ __launch_bounds__(256) void label_kernel(const int* __restrict__ lraw) {
    __shared__ int any;
    __shared__ int hist[NCLS];
    int t = threadIdx.x;
    if (t == 0) any = 0;
    if (t < NCLS) hist[t] = 0;
    __syncthreads();
    int acc = 0;
    for (int w = 1 + 2 * t; w < NN; w += 512) acc |= lraw[w];
    if (acc) atomicOr(&any, 1);
    __syncthreads();
    bool is64 = (any == 0);
    if (is64) {
        const long long* l64 = (const long long*)lraw;
        for (int i = t; i < NN; i += 256) g_lab[i] = (int)l64[i];
    } else {
        for (int i = t; i < NN; i += 256) g_lab[i] = lraw[i];
    }
    __syncthreads();
    for (int i = t; i < NN; i += 256) atomicAdd(&hist[g_lab[i]], 1);
    __syncthreads();
    for (int i = t; i < NN; i += 256) g_cnt[i] = (float)(hist[g_lab[i]] - 1);
}

// Normalize each row, convert to bf16.
__global__ __launch_bounds__(128) void prep_kernel(const float* __restrict__ reps) {
    int i = blockIdx.x;
    int t = threadIdx.x;
    const float4* row = (const float4*)(reps + (size_t)i * DD);
    float4 v = row[t];
    float ss = v.x * v.x + v.y * v.y + v.z * v.z + v.w * v.w;
    #pragma unroll
    for (int o = 16; o > 0; o >>= 1) ss += __shfl_down_sync(0xffffffffu, ss, o);
    __shared__ float ws[4];
    if ((t & 31) == 0) ws[t >> 5] = ss;
    __syncthreads();
    float tot = ws[0] + ws[1] + ws[2] + ws[3];
    float nrm = sqrtf(tot);
    float rn = (nrm > 1e-20f) ? (1.0f / nrm) : 0.0f;
    __nv_bfloat162* bp = (__nv_bfloat162*)(g_bf + (size_t)i * DD + (size_t)t * 4);
    bp[0] = __nv_bfloat162{__float2bfloat16(v.x * rn), __float2bfloat16(v.y * rn)};
    bp[1] = __nv_bfloat162{__float2bfloat16(v.z * rn), __float2bfloat16(v.w * rn)};
}

// ---------------------------------------------------------------------------
// Fused HMMA Gram + contrastive row-sum epilogue.
// 1-D triangular grid (2080 CTAs), 128x128 tile each.  PURE bf16 single pass
// (3-term split dropped: rel_err floor 1.06e-7 was reference-comparison noise,
// identical for fp32 SIMT and split-bf16 — budget analysis gives ~2e-5 here).
// 512 threads, 16 warps (4x4), warp tile 32x32.  KC=64 (8 chunks), 3-stage
// cp.async pipeline, one barrier per chunk.  Diag tiles: B aliases A.
// ---------------------------------------------------------------------------
#define KC 64
#define ROWB 144                        // 128B data + 16B pad (conflict-free)
#define TILEB (128 * ROWB)              // 18432 B per matrix
#define BUFB (2 * TILEB)                // A, B
#define NSTAGE 3
#define DSMEM_BYTES (NSTAGE * BUFB)     // 110592

__global__ __launch_bounds__(512) void gram_kernel() {
    // Triangular index -> (by, bx), bx >= by.
    int tidx = blockIdx.x;
    int by = (int)((2.0 * NTILE + 1.0 - sqrt((2.0 * NTILE + 1.0) * (2.0 * NTILE + 1.0)
                                             - 8.0 * (double)tidx)) * 0.5);
    while ((by + 1) * (2 * NTILE - by) / 2 <= tidx) by++;
    while (by * (2 * NTILE - by + 1) / 2 > tidx) by--;
    int bx = by + (tidx - by * (2 * NTILE - by + 1) / 2);

    extern __shared__ char dsmem[];
    __shared__ float s_rps[128], s_rng[128], s_cps[128], s_cng[128];
    __shared__ int s_labA[128], s_labB[128];

    int tid = threadIdx.x;
    int lane = tid & 31;
    int wid = tid >> 5;          // 0..15
    int warp_m = wid >> 2;       // 0..3
    int warp_n = wid & 3;        // 0..3
    bool diag = (bx == by);
    int bm = by << 7, bn = bx << 7;

    uint32_t sbase = smem_u32(dsmem);

    if (tid < 128) {
        s_labA[tid] = g_lab[bm + tid];
        s_labB[tid] = g_lab[bn + tid];
        s_rps[tid] = 0.0f; s_rng[tid] = 0.0f;
        s_cps[tid] = 0.0f; s_cng[tid] = 0.0f;
    }

    // ---- async tile loader (chunk c -> stage s) ----
    // KC=64: 128 rows x 8 x 16B segments = 1024 units = 2 per thread per matrix.
    auto load_chunk = [&](int c, int s) {
        int k0 = c * KC;
        uint32_t sb = sbase + s * BUFB;
        #pragma unroll
        for (int it = 0; it < 2; it++) {
            int u = tid + it * 512;
            int row = u >> 3;
            int seg = u & 7;
            uint32_t soff = row * ROWB + seg * 16;
            CP_ASYNC16(sb + soff, g_bf + (size_t)(bm + row) * DD + k0 + seg * 8);
            if (!diag)
                CP_ASYNC16(sb + TILEB + soff, g_bf + (size_t)(bn + row) * DD + k0 + seg * 8);
        }
    };

    float acc[2][4][4];
    #pragma unroll
    for (int mt = 0; mt < 2; mt++)
        #pragma unroll
        for (int nt = 0; nt < 4; nt++)
            #pragma unroll
            for (int e = 0; e < 4; e++) acc[mt][nt][e] = 0.0f;

    // Prologue: 2 chunks of runway.
    load_chunk(0, 0); CP_COMMIT();
    load_chunk(1, 1); CP_COMMIT();

    uint32_t boffB = diag ? 0u : (uint32_t)TILEB;   // B aliases A on diag

    const int NCHUNK = DD / KC;  // 8
    int stage = 0;
    for (int c = 0; c < NCHUNK; c++) {
        if (c < NCHUNK - 1) CP_WAIT1(); else CP_WAIT0();
        __syncthreads();
        if (c + 2 < NCHUNK) {
            int ns = stage + 2; if (ns >= NSTAGE) ns -= NSTAGE;
            load_chunk(c + 2, ns);
            CP_COMMIT();
        }

        uint32_t ab = sbase + stage * BUFB;          // A tile
        uint32_t bb = ab + boffB;                    // B tile

        #pragma unroll
        for (int ks = 0; ks < 4; ks++) {
            int k0 = ks * 16;
            // B fragments: two x4 loads cover 32 n-rows at k0/k0+8
            uint32_t bh[8];
            #pragma unroll
            for (int p = 0; p < 2; p++) {
                int nrow = warp_n * 32 + p * 16 + (lane & 7) + ((lane >> 4) << 3);
                int koff = k0 + ((lane >> 3) & 1) * 8;
                LDSM4(bh[p*4+0], bh[p*4+1], bh[p*4+2], bh[p*4+3],
                      bb + nrow * ROWB + koff * 2);
            }
            #pragma unroll
            for (int mt = 0; mt < 2; mt++) {
                int arow = warp_m * 32 + mt * 16 + (lane & 15);
                int koff = k0 + (lane >> 4) * 8;
                uint32_t ah0, ah1, ah2, ah3;
                LDSM4(ah0, ah1, ah2, ah3, ab + arow * ROWB + koff * 2);
                #pragma unroll
                for (int nt = 0; nt < 4; nt++) {
                    int bi = (nt >> 1) * 4 + (nt & 1) * 2;
                    MMA16816(acc[mt][nt], ah0, ah1, ah2, ah3, bh[bi], bh[bi+1]);
                }
            }
        }
        stage++; if (stage >= NSTAGE) stage -= NSTAGE;
        // No trailing barrier: stage reuse (distance 2) is ordered by the
        // next iterations' top barriers.
    }

    // ---------------- fused contrastive epilogue ----------------
    __syncthreads();
    int qid = lane >> 2;        // 0..7
    int cpos = lane & 3;        // 0..3
    float rowPS[2][2], rowNG[2][2], colPS[4][2], colNG[4][2];
    #pragma unroll
    for (int a = 0; a < 2; a++)
        #pragma unroll
        for (int h = 0; h < 2; h++) { rowPS[a][h] = 0.0f; rowNG[a][h] = 0.0f; }
    #pragma unroll
    for (int a = 0; a < 4; a++)
        #pragma unroll
        for (int h = 0; h < 2; h++) { colPS[a][h] = 0.0f; colNG[a][h] = 0.0f; }

    #pragma unroll
    for (int mt = 0; mt < 2; mt++) {
        #pragma unroll
        for (int half = 0; half < 2; half++) {
            int il = warp_m * 32 + mt * 16 + qid + half * 8;
            int li = s_labA[il];
            int gi = bm + il;
            #pragma unroll
            for (int nt = 0; nt < 4; nt++) {
                #pragma unroll
                for (int b = 0; b < 2; b++) {
                    int jl = warp_n * 32 + nt * 8 + cpos * 2 + b;
                    float g = acc[mt][nt][half * 2 + b];
                    float s = fmaf(g, 5.0f, 5.0f + 1e-7f);
                    bool same = (s_labB[jl] == li);
                    bool isd = (gi == bn + jl);
                    float pc = (same && !isd) ? s : 0.0f;
                    float e  = same ? 0.0f : __expf(s);
                    rowPS[mt][half] += pc;  rowNG[mt][half] += e;
                    colPS[nt][b]    += pc;  colNG[nt][b]    += e;
                }
            }
        }
    }
    #pragma unroll
    for (int mt = 0; mt < 2; mt++)
        #pragma unroll
        for (int half = 0; half < 2; half++) {
            int il = warp_m * 32 + mt * 16 + qid + half * 8;
            atomicAdd(&s_rps[il], rowPS[mt][half]);
            atomicAdd(&s_rng[il], rowNG[mt][half]);
        }
    if (!diag) {
        #pragma unroll
        for (int nt = 0; nt < 4; nt++)
            #pragma unroll
            for (int b = 0; b < 2; b++) {
                int jl = warp_n * 32 + nt * 8 + cpos * 2 + b;
                atomicAdd(&s_cps[jl], colPS[nt][b]);
                atomicAdd(&s_cng[jl], colNG[nt][b]);
            }
    }
    __syncthreads();
    if (tid < 128) {
        atomicAdd(&g_ps[bm + tid], s_rps[tid]);
        atomicAdd(&g_ng[bm + tid], s_rng[tid]);
        if (!diag) {
            atomicAdd(&g_ps[bn + tid], s_cps[tid]);
            atomicAdd(&g_ng[bn + tid], s_cng[tid]);
        }
    }
}

// ---------------------------------------------------------------------------
// Final: loss_i = -ps/(cnt+eps) + log(ng+eps); masked mean of loss>0.
// (Global max-shift cancels analytically to ~1e-9 absolute — omitted.)
// ---------------------------------------------------------------------------
__global__ __launch_bounds__(256) void loss_kernel(float* __restrict__ out) {
    int t = threadIdx.x;
    float s = 0.0f, c = 0.0f;
    for (int i = t; i < NN; i += 256) {
        float l = -g_ps[i] / (g_cnt[i] + 1e-8f) + logf(g_ng[i] + 1e-8f);
        if (l > 0.0f) { s += l; c += 1.0f; }
    }
    #pragma unroll
    for (int o = 16; o > 0; o >>= 1) {
        s += __shfl_down_sync(0xffffffffu, s, o);
        c += __shfl_down_sync(0xffffffffu, c, o);
    }
    __shared__ float ssum[8], scnt[8];
    if ((t & 31) == 0) { ssum[t >> 5] = s; scnt[t >> 5] = c; }
    __syncthreads();
    if (t == 0) {
        float S = 0.0f, C = 0.0f;
        #pragma unroll
        for (int w = 0; w < 8; w++) { S += ssum[w]; C += scnt[w]; }
        out[0] = S / (C + 1e-8f);
    }
}

// ---------------------------------------------------------------------------
extern "C" void kernel_launch(void* const* d_in, const int* in_sizes, int n_in,
                              void* d_out, int out_size) {
    (void)in_sizes; (void)n_in; (void)out_size;
    const float* reps = (const float*)d_in[0];
    const int*   lraw = (const int*)d_in[1];
    float*       out  = (float*)d_out;

    cudaFuncSetAttribute(gram_kernel, cudaFuncAttributeMaxDynamicSharedMemorySize,
                         DSMEM_BYTES);

    init_sums_kernel<<<(NN + 255) / 256, 256>>>();
    label_kernel<<<1, 256>>>(lraw);
    prep_kernel<<<NN, 128>>>(reps);
    gram_kernel<<<NTRI, 512, DSMEM_BYTES>>>();
    loss_kernel<<<1, 256>>>(out);
}

// round 15
// speedup vs baseline: 3.6478x; 1.4869x over previous
#include <cuda_runtime.h>
#include <cuda_bf16.h>
#include <cstdint>
#include <cmath>

#define NN 8192
#define DD 512
#define NCLS 100
#define NTILE 64                         // 8192/128 tiles per side
#define NTRI (NTILE * (NTILE + 1) / 2)   // 2080 upper-tri tiles

// ---------------------------------------------------------------------------
// Device globals
// ---------------------------------------------------------------------------
static __device__ __nv_bfloat16 g_bf[NN * DD];   // 8 MB normalized bf16 reps
static __device__ int   g_lab[NN];
static __device__ float g_cnt[NN];               // (#same-label) - 1
static __device__ float g_ps[NN];                // sum of pos scores (raw)
static __device__ float g_ng[NN];                // sum of exp(neg scores)

// ---------------------------------------------------------------------------
// Baseline-ISA PTX helpers (no 'a'-features: works at target sm_103)
// ---------------------------------------------------------------------------
__device__ __forceinline__ uint32_t smem_u32(const void* p) {
    uint32_t a;
    asm("{ .reg .u64 t; cvta.to.shared.u64 t, %1; cvt.u32.u64 %0, t; }" : "=r"(a) : "l"(p));
    return a;
}

#define CP_ASYNC16(saddr, gaddr) \
    asm volatile("cp.async.cg.shared.global [%0], [%1], 16;" :: "r"(saddr), "l"(gaddr) : "memory")
#define CP_COMMIT() asm volatile("cp.async.commit_group;" ::: "memory")
#define CP_WAIT0()  asm volatile("cp.async.wait_group 0;" ::: "memory")
#define CP_WAIT1()  asm volatile("cp.async.wait_group 1;" ::: "memory")

#define LDSM4(r0, r1, r2, r3, addr) \
    asm volatile("ldmatrix.sync.aligned.m8n8.x4.shared.b16 {%0,%1,%2,%3}, [%4];" \
                 : "=r"(r0), "=r"(r1), "=r"(r2), "=r"(r3) : "r"(addr))

#define MMA16816(c, a0, a1, a2, a3, b0, b1) \
    asm volatile("mma.sync.aligned.m16n8k16.row.col.f32.bf16.bf16.f32 " \
                 "{%0,%1,%2,%3}, {%4,%5,%6,%7}, {%8,%9}, {%0,%1,%2,%3};" \
                 : "+f"((c)[0]), "+f"((c)[1]), "+f"((c)[2]), "+f"((c)[3]) \
                 : "r"(a0), "r"(a1), "r"(a2), "r"(a3), "r"(b0), "r"(b1))

// ---------------------------------------------------------------------------
// Small kernels
// ---------------------------------------------------------------------------
__global__ __launch_bounds__(256) void init_sums_kernel() {
    int i = blockIdx.x * 256 + threadIdx.x;
    if (i < NN) { g_ps[i] = 0.0f; g_ng[i] = 0.0f; }
}

// Detect int64 vs int32 labels, fill g_lab, build per-row same-label count.
__global__ __launch_bounds__(256) void label_kernel(const int* __restrict__ lraw) {
    __shared__ int any;
    __shared__ int hist[NCLS];
    int t = threadIdx.x;
    if (t == 0) any = 0;
    if (t < NCLS) hist[t] = 0;
    __syncthreads();
    int acc = 0;
    for (int w = 1 + 2 * t; w < NN; w += 512) acc |= lraw[w];
    if (acc) atomicOr(&any, 1);
    __syncthreads();
    bool is64 = (any == 0);
    if (is64) {
        const long long* l64 = (const long long*)lraw;
        for (int i = t; i < NN; i += 256) g_lab[i] = (int)l64[i];
    } else {
        for (int i = t; i < NN; i += 256) g_lab[i] = lraw[i];
    }
    __syncthreads();
    for (int i = t; i < NN; i += 256) atomicAdd(&hist[g_lab[i]], 1);
    __syncthreads();
    for (int i = t; i < NN; i += 256) g_cnt[i] = (float)(hist[g_lab[i]] - 1);
}

// Normalize each row, convert to bf16.
__global__ __launch_bounds__(128) void prep_kernel(const float* __restrict__ reps) {
    int i = blockIdx.x;
    int t = threadIdx.x;
    const float4* row = (const float4*)(reps + (size_t)i * DD);
    float4 v = row[t];
    float ss = v.x * v.x + v.y * v.y + v.z * v.z + v.w * v.w;
    #pragma unroll
    for (int o = 16; o > 0; o >>= 1) ss += __shfl_down_sync(0xffffffffu, ss, o);
    __shared__ float ws[4];
    if ((t & 31) == 0) ws[t >> 5] = ss;
    __syncthreads();
    float tot = ws[0] + ws[1] + ws[2] + ws[3];
    float nrm = sqrtf(tot);
    float rn = (nrm > 1e-20f) ? (1.0f / nrm) : 0.0f;
    __nv_bfloat162* bp = (__nv_bfloat162*)(g_bf + (size_t)i * DD + (size_t)t * 4);
    bp[0] = __nv_bfloat162{__float2bfloat16(v.x * rn), __float2bfloat16(v.y * rn)};
    bp[1] = __nv_bfloat162{__float2bfloat16(v.z * rn), __float2bfloat16(v.w * rn)};
}

// ---------------------------------------------------------------------------
// Fused HMMA Gram + contrastive row-sum epilogue.
// 1-D triangular grid (2080 CTAs), 128x128 tile each, pure bf16 single pass.
// R15: 256 threads, 8 warps (2x4), warp tile 64x32 (bytes/MAC x0.75 vs 32x32 —
// L1 crossbar was the R14 wall at 63.8%), fragment double-buffering (B ks+1
// prefetch, A mt+1 prefetch) to hide LDSM->MMA latency, shuffle-reduced
// epilogue atomics.  KC=64, 3-stage cp.async, 1 barrier/chunk, 2 CTA/SM.
// ---------------------------------------------------------------------------
#define KC 64
#define ROWB 144                        // 128B data + 16B pad (conflict-free)
#define TILEB (128 * ROWB)              // 18432 B per matrix
#define BUFB (2 * TILEB)                // A, B
#define NSTAGE 3
#define DSMEM_BYTES (NSTAGE * BUFB)     // 110592  (<= 113.5KB -> 2 CTA/SM)

__global__ __launch_bounds__(256, 2) void gram_kernel() {
    // Triangular index -> (by, bx), bx >= by.
    int tidx = blockIdx.x;
    int by = (int)((2.0 * NTILE + 1.0 - sqrt((2.0 * NTILE + 1.0) * (2.0 * NTILE + 1.0)
                                             - 8.0 * (double)tidx)) * 0.5);
    while ((by + 1) * (2 * NTILE - by) / 2 <= tidx) by++;
    while (by * (2 * NTILE - by + 1) / 2 > tidx) by--;
    int bx = by + (tidx - by * (2 * NTILE - by + 1) / 2);

    extern __shared__ char dsmem[];
    __shared__ float s_rps[128], s_rng[128], s_cps[128], s_cng[128];
    __shared__ int s_labA[128], s_labB[128];

    int tid = threadIdx.x;
    int lane = tid & 31;
    int wid = tid >> 5;          // 0..7
    int warp_m = wid >> 2;       // 0..1
    int warp_n = wid & 3;        // 0..3
    bool diag = (bx == by);
    int bm = by << 7, bn = bx << 7;

    uint32_t sbase = smem_u32(dsmem);

    if (tid < 128) {
        s_labA[tid] = g_lab[bm + tid];
        s_labB[tid] = g_lab[bn + tid];
        s_rps[tid] = 0.0f; s_rng[tid] = 0.0f;
        s_cps[tid] = 0.0f; s_cng[tid] = 0.0f;
    }

    // ---- async tile loader (chunk c -> stage s) ----
    // KC=64: 128 rows x 8 x 16B = 1024 units per matrix; 256 threads -> 4 its.
    auto load_chunk = [&](int c, int s) {
        int k0 = c * KC;
        uint32_t sb = sbase + s * BUFB;
        #pragma unroll
        for (int it = 0; it < 4; it++) {
            int u = tid + it * 256;
            int row = u >> 3;
            int seg = u & 7;
            uint32_t soff = row * ROWB + seg * 16;
            CP_ASYNC16(sb + soff, g_bf + (size_t)(bm + row) * DD + k0 + seg * 8);
            if (!diag)
                CP_ASYNC16(sb + TILEB + soff, g_bf + (size_t)(bn + row) * DD + k0 + seg * 8);
        }
    };

    float acc[4][4][4];
    #pragma unroll
    for (int mt = 0; mt < 4; mt++)
        #pragma unroll
        for (int nt = 0; nt < 4; nt++)
            #pragma unroll
            for (int e = 0; e < 4; e++) acc[mt][nt][e] = 0.0f;

    // Prologue: 2 chunks of runway.
    load_chunk(0, 0); CP_COMMIT();
    load_chunk(1, 1); CP_COMMIT();

    uint32_t boffB = diag ? 0u : (uint32_t)TILEB;   // B aliases A on diag

    // Per-lane fragment addresses (constant across chunks/ks except k offset).
    int b_nrow = warp_n * 32 + (lane & 7) + ((lane >> 4) << 3);  // +p*16
    int b_koff = ((lane >> 3) & 1) * 8;                          // +k0
    int a_row  = warp_m * 64 + (lane & 15);                      // +mt*16
    int a_koff = (lane >> 4) * 8;                                // +k0

    const int NCHUNK = DD / KC;  // 8
    int stage = 0;
    for (int c = 0; c < NCHUNK; c++) {
        if (c < NCHUNK - 1) CP_WAIT1(); else CP_WAIT0();
        __syncthreads();
        if (c + 2 < NCHUNK) {
            int ns = stage + 2; if (ns >= NSTAGE) ns -= NSTAGE;
            load_chunk(c + 2, ns);
            CP_COMMIT();
        }

        uint32_t ab = sbase + stage * BUFB;          // A tile
        uint32_t bb = ab + boffB;                    // B tile

        // B fragments double-buffered across ks.
        uint32_t bh[2][8];
        {   // load ks=0
            uint32_t base = bb + b_koff * 2;
            LDSM4(bh[0][0], bh[0][1], bh[0][2], bh[0][3], base + b_nrow * ROWB);
            LDSM4(bh[0][4], bh[0][5], bh[0][6], bh[0][7], base + (b_nrow + 16) * ROWB);
        }
        #pragma unroll
        for (int ks = 0; ks < 4; ks++) {
            int cur = ks & 1, nxt = cur ^ 1;
            if (ks < 3) {   // prefetch B for ks+1
                uint32_t base = bb + ((ks + 1) * 16 + b_koff) * 2;
                LDSM4(bh[nxt][0], bh[nxt][1], bh[nxt][2], bh[nxt][3], base + b_nrow * ROWB);
                LDSM4(bh[nxt][4], bh[nxt][5], bh[nxt][6], bh[nxt][7], base + (b_nrow + 16) * ROWB);
            }
            uint32_t abase = ab + (ks * 16 + a_koff) * 2;
            uint32_t a0[4], a1[4];
            LDSM4(a0[0], a0[1], a0[2], a0[3], abase + a_row * ROWB);
            #pragma unroll
            for (int mt = 0; mt < 4; mt++) {
                uint32_t* ac = (mt & 1) ? a1 : a0;
                uint32_t* an = (mt & 1) ? a0 : a1;
                if (mt < 3)   // prefetch A for mt+1
                    LDSM4(an[0], an[1], an[2], an[3], abase + (a_row + (mt + 1) * 16) * ROWB);
                #pragma unroll
                for (int nt = 0; nt < 4; nt++) {
                    int bi = (nt >> 1) * 4 + (nt & 1) * 2;
                    MMA16816(acc[mt][nt], ac[0], ac[1], ac[2], ac[3],
                             bh[cur][bi], bh[cur][bi + 1]);
                }
            }
        }
        stage++; if (stage >= NSTAGE) stage -= NSTAGE;
        // No trailing barrier: stage reuse (distance 2) ordered by later top barriers.
    }

    // ---------------- fused contrastive epilogue ----------------
    __syncthreads();
    int qid = lane >> 2;        // 0..7
    int cpos = lane & 3;        // 0..3
    float colPS[4][2], colNG[4][2];
    #pragma unroll
    for (int a = 0; a < 4; a++)
        #pragma unroll
        for (int h = 0; h < 2; h++) { colPS[a][h] = 0.0f; colNG[a][h] = 0.0f; }

    #pragma unroll
    for (int mt = 0; mt < 4; mt++) {
        #pragma unroll
        for (int half = 0; half < 2; half++) {
            int il = warp_m * 64 + mt * 16 + qid + half * 8;
            int li = s_labA[il];
            int gi = bm + il;
            float rps = 0.0f, rng = 0.0f;
            #pragma unroll
            for (int nt = 0; nt < 4; nt++) {
                #pragma unroll
                for (int b = 0; b < 2; b++) {
                    int jl = warp_n * 32 + nt * 8 + cpos * 2 + b;
                    float g = acc[mt][nt][half * 2 + b];
                    float s = fmaf(g, 5.0f, 5.0f + 1e-7f);
                    bool same = (s_labB[jl] == li);
                    bool isd = (gi == bn + jl);
                    float pc = (same && !isd) ? s : 0.0f;
                    float e  = same ? 0.0f : __expf(s);
                    rps += pc;  rng += e;
                    colPS[nt][b] += pc;  colNG[nt][b] += e;
                }
            }
            // reduce over cpos lanes (xor 1,2), one atomic per il
            rps += __shfl_xor_sync(0xffffffffu, rps, 1);
            rps += __shfl_xor_sync(0xffffffffu, rps, 2);
            rng += __shfl_xor_sync(0xffffffffu, rng, 1);
            rng += __shfl_xor_sync(0xffffffffu, rng, 2);
            if (cpos == 0) {
                atomicAdd(&s_rps[il], rps);
                atomicAdd(&s_rng[il], rng);
            }
        }
    }
    if (!diag) {
        #pragma unroll
        for (int nt = 0; nt < 4; nt++)
            #pragma unroll
            for (int b = 0; b < 2; b++) {
                float p = colPS[nt][b], n = colNG[nt][b];
                p += __shfl_xor_sync(0xffffffffu, p, 4);
                p += __shfl_xor_sync(0xffffffffu, p, 8);
                p += __shfl_xor_sync(0xffffffffu, p, 16);
                n += __shfl_xor_sync(0xffffffffu, n, 4);
                n += __shfl_xor_sync(0xffffffffu, n, 8);
                n += __shfl_xor_sync(0xffffffffu, n, 16);
                if (qid == 0) {
                    int jl = warp_n * 32 + nt * 8 + cpos * 2 + b;
                    atomicAdd(&s_cps[jl], p);
                    atomicAdd(&s_cng[jl], n);
                }
            }
    }
    __syncthreads();
    if (tid < 128) {
        atomicAdd(&g_ps[bm + tid], s_rps[tid]);
        atomicAdd(&g_ng[bm + tid], s_rng[tid]);
        if (!diag) {
            atomicAdd(&g_ps[bn + tid], s_cps[tid]);
            atomicAdd(&g_ng[bn + tid], s_cng[tid]);
        }
    }
}

// ---------------------------------------------------------------------------
// Final: loss_i = -ps/(cnt+eps) + log(ng+eps); masked mean of loss>0.
// (Global max-shift cancels analytically to ~1e-9 absolute — omitted.)
// ---------------------------------------------------------------------------
__global__ __launch_bounds__(256) void loss_kernel(float* __restrict__ out) {
    int t = threadIdx.x;
    float s = 0.0f, c = 0.0f;
    for (int i = t; i < NN; i += 256) {
        float l = -g_ps[i] / (g_cnt[i] + 1e-8f) + logf(g_ng[i] + 1e-8f);
        if (l > 0.0f) { s += l; c += 1.0f; }
    }
    #pragma unroll
    for (int o = 16; o > 0; o >>= 1) {
        s += __shfl_down_sync(0xffffffffu, s, o);
        c += __shfl_down_sync(0xffffffffu, c, o);
    }
    __shared__ float ssum[8], scnt[8];
    if ((t & 31) == 0) { ssum[t >> 5] = s; scnt[t >> 5] = c; }
    __syncthreads();
    if (t == 0) {
        float S = 0.0f, C = 0.0f;
        #pragma unroll
        for (int w = 0; w < 8; w++) { S += ssum[w]; C += scnt[w]; }
        out[0] = S / (C + 1e-8f);
    }
}

// ---------------------------------------------------------------------------
extern "C" void kernel_launch(void* const* d_in, const int* in_sizes, int n_in,
                              void* d_out, int out_size) {
    (void)in_sizes; (void)n_in; (void)out_size;
    const float* reps = (const float*)d_in[0];
    const int*   lraw = (const int*)d_in[1];
    float*       out  = (float*)d_out;

    cudaFuncSetAttribute(gram_kernel, cudaFuncAttributeMaxDynamicSharedMemorySize,
                         DSMEM_BYTES);

    init_sums_kernel<<<(NN + 255) / 256, 256>>>();
    label_kernel<<<1, 256>>>(lraw);
    prep_kernel<<<NN, 128>>>(reps);
    gram_kernel<<<NTRI, 256, DSMEM_BYTES>>>();
    loss_kernel<<<1, 256>>>(out);
}

// round 16
// speedup vs baseline: 3.8057x; 1.0433x over previous
#include <cuda_runtime.h>
#include <cuda_bf16.h>
#include <cstdint>
#include <cmath>

#define NN 8192
#define DD 512
#define NCLS 100
#define NTILE 64                         // 8192/128 tiles per side
#define NTRI (NTILE * (NTILE + 1) / 2)   // 2080 upper-tri tiles

// ---------------------------------------------------------------------------
// Device globals
// ---------------------------------------------------------------------------
static __device__ __nv_bfloat16 g_bf[NN * DD];   // 8 MB normalized bf16 reps
static __device__ int   g_lab[NN];
static __device__ int   g_hist[NCLS];            // class histogram
static __device__ float g_ps[NN];                // sum of pos scores (raw)
static __device__ float g_ng[NN];                // sum of exp(neg scores)

// ---------------------------------------------------------------------------
// Baseline-ISA PTX helpers (no 'a'-features: works at target sm_103)
// ---------------------------------------------------------------------------
__device__ __forceinline__ uint32_t smem_u32(const void* p) {
    uint32_t a;
    asm("{ .reg .u64 t; cvta.to.shared.u64 t, %1; cvt.u32.u64 %0, t; }" : "=r"(a) : "l"(p));
    return a;
}

#define CP_ASYNC16(saddr, gaddr) \
    asm volatile("cp.async.cg.shared.global [%0], [%1], 16;" :: "r"(saddr), "l"(gaddr) : "memory")
#define CP_COMMIT() asm volatile("cp.async.commit_group;" ::: "memory")
#define CP_WAIT0()  asm volatile("cp.async.wait_group 0;" ::: "memory")
#define CP_WAIT1()  asm volatile("cp.async.wait_group 1;" ::: "memory")

#define LDSM4(r0, r1, r2, r3, addr) \
    asm volatile("ldmatrix.sync.aligned.m8n8.x4.shared.b16 {%0,%1,%2,%3}, [%4];" \
                 : "=r"(r0), "=r"(r1), "=r"(r2), "=r"(r3) : "r"(addr))

#define MMA16816(c, a0, a1, a2, a3, b0, b1) \
    asm volatile("mma.sync.aligned.m16n8k16.row.col.f32.bf16.bf16.f32 " \
                 "{%0,%1,%2,%3}, {%4,%5,%6,%7}, {%8,%9}, {%0,%1,%2,%3};" \
                 : "+f"((c)[0]), "+f"((c)[1]), "+f"((c)[2]), "+f"((c)[3]) \
                 : "r"(a0), "r"(a1), "r"(a2), "r"(a3), "r"(b0), "r"(b1))

// ---------------------------------------------------------------------------
// Small kernels
// ---------------------------------------------------------------------------
// Zero per-row sums and the class histogram.
__global__ __launch_bounds__(256) void init_kernel() {
    int i = blockIdx.x * 256 + threadIdx.x;
    if (i < NN) { g_ps[i] = 0.0f; g_ng[i] = 0.0f; }
    if (blockIdx.x == 0 && threadIdx.x < NCLS) g_hist[threadIdx.x] = 0;
}

// 32 blocks x 256: per-block int64/int32 detection + label convert + smem hist
// -> global hist atomics.  Detection reads words 512*(b&15)+odd: in-bounds for
// both dtypes; for int64 these are high halves (all zero), for int32 random
// labels (P(all 256 zero) ~ 100^-256).
__global__ __launch_bounds__(256) void label_kernel(const int* __restrict__ lraw) {
    __shared__ int any;
    __shared__ int hist[NCLS];
    int t = threadIdx.x;
    int b = blockIdx.x;
    if (t == 0) any = 0;
    if (t < NCLS) hist[t] = 0;
    __syncthreads();
    int wbase = 512 * (b & 15);
    if (lraw[wbase + 2 * t + 1]) atomicOr(&any, 1);
    __syncthreads();
    bool is64 = (any == 0);
    int i = b * 256 + t;
    int lab = is64 ? (int)((const long long*)lraw)[i] : lraw[i];
    g_lab[i] = lab;
    atomicAdd(&hist[lab], 1);
    __syncthreads();
    if (t < NCLS && hist[t] > 0) atomicAdd(&g_hist[t], hist[t]);
}

// Normalize each row, convert to bf16.
__global__ __launch_bounds__(128) void prep_kernel(const float* __restrict__ reps) {
    int i = blockIdx.x;
    int t = threadIdx.x;
    const float4* row = (const float4*)(reps + (size_t)i * DD);
    float4 v = row[t];
    float ss = v.x * v.x + v.y * v.y + v.z * v.z + v.w * v.w;
    #pragma unroll
    for (int o = 16; o > 0; o >>= 1) ss += __shfl_down_sync(0xffffffffu, ss, o);
    __shared__ float ws[4];
    if ((t & 31) == 0) ws[t >> 5] = ss;
    __syncthreads();
    float tot = ws[0] + ws[1] + ws[2] + ws[3];
    float nrm = sqrtf(tot);
    float rn = (nrm > 1e-20f) ? (1.0f / nrm) : 0.0f;
    __nv_bfloat162* bp = (__nv_bfloat162*)(g_bf + (size_t)i * DD + (size_t)t * 4);
    bp[0] = __nv_bfloat162{__float2bfloat16(v.x * rn), __float2bfloat16(v.y * rn)};
    bp[1] = __nv_bfloat162{__float2bfloat16(v.z * rn), __float2bfloat16(v.w * rn)};
}

// ---------------------------------------------------------------------------
// Fused HMMA Gram + contrastive row-sum epilogue.
// 1-D triangular grid (2080 CTAs), 128x128 tile each, pure bf16 single pass.
// 256 threads, 8 warps (2x4), warp tile 64x32; KC=64, 3-stage cp.async.
// R16: chunk-head reorder (ks0 LDSMs issue BEFORE the next-chunk cp.async
// batch) + A-fragment prefetch chain closed across ks (mt=3 prefetches
// A(ks+1, mt=0)) so no ks starts with a cold LDSM->MMA stall.
// ---------------------------------------------------------------------------
#define KC 64
#define ROWB 144                        // 128B data + 16B pad (conflict-free)
#define TILEB (128 * ROWB)              // 18432 B per matrix
#define BUFB (2 * TILEB)                // A, B
#define NSTAGE 3
#define DSMEM_BYTES (NSTAGE * BUFB)     // 110592  (2 CTA/SM)

__global__ __launch_bounds__(256, 2) void gram_kernel() {
    // Triangular index -> (by, bx), bx >= by.
    int tidx = blockIdx.x;
    int by = (int)((2.0 * NTILE + 1.0 - sqrt((2.0 * NTILE + 1.0) * (2.0 * NTILE + 1.0)
                                             - 8.0 * (double)tidx)) * 0.5);
    while ((by + 1) * (2 * NTILE - by) / 2 <= tidx) by++;
    while (by * (2 * NTILE - by + 1) / 2 > tidx) by--;
    int bx = by + (tidx - by * (2 * NTILE - by + 1) / 2);

    extern __shared__ char dsmem[];
    __shared__ float s_rps[128], s_rng[128], s_cps[128], s_cng[128];
    __shared__ int s_labA[128], s_labB[128];

    int tid = threadIdx.x;
    int lane = tid & 31;
    int wid = tid >> 5;          // 0..7
    int warp_m = wid >> 2;       // 0..1
    int warp_n = wid & 3;        // 0..3
    bool diag = (bx == by);
    int bm = by << 7, bn = bx << 7;

    uint32_t sbase = smem_u32(dsmem);

    if (tid < 128) {
        s_labA[tid] = g_lab[bm + tid];
        s_labB[tid] = g_lab[bn + tid];
        s_rps[tid] = 0.0f; s_rng[tid] = 0.0f;
        s_cps[tid] = 0.0f; s_cng[tid] = 0.0f;
    }

    // ---- async tile loader (chunk c -> stage s) ----
    auto load_chunk = [&](int c, int s) {
        int k0 = c * KC;
        uint32_t sb = sbase + s * BUFB;
        #pragma unroll
        for (int it = 0; it < 4; it++) {
            int u = tid + it * 256;
            int row = u >> 3;
            int seg = u & 7;
            uint32_t soff = row * ROWB + seg * 16;
            CP_ASYNC16(sb + soff, g_bf + (size_t)(bm + row) * DD + k0 + seg * 8);
            if (!diag)
                CP_ASYNC16(sb + TILEB + soff, g_bf + (size_t)(bn + row) * DD + k0 + seg * 8);
        }
    };

    float acc[4][4][4];
    #pragma unroll
    for (int mt = 0; mt < 4; mt++)
        #pragma unroll
        for (int nt = 0; nt < 4; nt++)
            #pragma unroll
            for (int e = 0; e < 4; e++) acc[mt][nt][e] = 0.0f;

    // Prologue: 2 chunks of runway.
    load_chunk(0, 0); CP_COMMIT();
    load_chunk(1, 1); CP_COMMIT();

    uint32_t boffB = diag ? 0u : (uint32_t)TILEB;   // B aliases A on diag

    // Per-lane fragment addresses.
    int b_nrow = warp_n * 32 + (lane & 7) + ((lane >> 4) << 3);  // +p*16
    int b_koff = ((lane >> 3) & 1) * 8;                          // +k0
    int a_row  = warp_m * 64 + (lane & 15);                      // +mt*16
    int a_koff = (lane >> 4) * 8;                                // +k0

    const int NCHUNK = DD / KC;  // 8
    int stage = 0;
    for (int c = 0; c < NCHUNK; c++) {
        if (c < NCHUNK - 1) CP_WAIT1(); else CP_WAIT0();
        __syncthreads();

        uint32_t ab = sbase + stage * BUFB;          // A tile
        uint32_t bb = ab + boffB;                    // B tile

        // Head fragment loads FIRST (critical path), then the non-urgent
        // next-chunk cp.async batch.
        uint32_t af[2][4];
        uint32_t bh[2][8];
        LDSM4(af[0][0], af[0][1], af[0][2], af[0][3],
              ab + a_koff * 2 + a_row * ROWB);                    // A ks0 mt0
        {
            uint32_t base = bb + b_koff * 2;
            LDSM4(bh[0][0], bh[0][1], bh[0][2], bh[0][3], base + b_nrow * ROWB);
            LDSM4(bh[0][4], bh[0][5], bh[0][6], bh[0][7], base + (b_nrow + 16) * ROWB);
        }
        if (c + 2 < NCHUNK) {
            int ns = stage + 2; if (ns >= NSTAGE) ns -= NSTAGE;
            load_chunk(c + 2, ns);
            CP_COMMIT();
        }

        #pragma unroll
        for (int ks = 0; ks < 4; ks++) {
            int cur = ks & 1, nxt = cur ^ 1;
            if (ks < 3) {   // prefetch B for ks+1
                uint32_t base = bb + ((ks + 1) * 16 + b_koff) * 2;
                LDSM4(bh[nxt][0], bh[nxt][1], bh[nxt][2], bh[nxt][3], base + b_nrow * ROWB);
                LDSM4(bh[nxt][4], bh[nxt][5], bh[nxt][6], bh[nxt][7], base + (b_nrow + 16) * ROWB);
            }
            uint32_t abase = ab + (ks * 16 + a_koff) * 2;
            #pragma unroll
            for (int mt = 0; mt < 4; mt++) {
                uint32_t* ac = af[mt & 1];
                uint32_t* an = af[(mt & 1) ^ 1];
                if (mt < 3) {          // prefetch A(ks, mt+1)
                    LDSM4(an[0], an[1], an[2], an[3],
                          abase + (a_row + (mt + 1) * 16) * ROWB);
                } else if (ks < 3) {   // prefetch A(ks+1, mt=0) across the seam
                    LDSM4(an[0], an[1], an[2], an[3],
                          ab + ((ks + 1) * 16 + a_koff) * 2 + a_row * ROWB);
                }
                #pragma unroll
                for (int nt = 0; nt < 4; nt++) {
                    int bi = (nt >> 1) * 4 + (nt & 1) * 2;
                    MMA16816(acc[mt][nt], ac[0], ac[1], ac[2], ac[3],
                             bh[cur][bi], bh[cur][bi + 1]);
                }
            }
        }
        stage++; if (stage >= NSTAGE) stage -= NSTAGE;
    }

    // ---------------- fused contrastive epilogue ----------------
    __syncthreads();
    int qid = lane >> 2;        // 0..7
    int cpos = lane & 3;        // 0..3
    float colPS[4][2], colNG[4][2];
    #pragma unroll
    for (int a = 0; a < 4; a++)
        #pragma unroll
        for (int h = 0; h < 2; h++) { colPS[a][h] = 0.0f; colNG[a][h] = 0.0f; }

    #pragma unroll
    for (int mt = 0; mt < 4; mt++) {
        #pragma unroll
        for (int half = 0; half < 2; half++) {
            int il = warp_m * 64 + mt * 16 + qid + half * 8;
            int li = s_labA[il];
            int gi = bm + il;
            float rps = 0.0f, rng = 0.0f;
            #pragma unroll
            for (int nt = 0; nt < 4; nt++) {
                #pragma unroll
                for (int b = 0; b < 2; b++) {
                    int jl = warp_n * 32 + nt * 8 + cpos * 2 + b;
                    float g = acc[mt][nt][half * 2 + b];
                    float s = fmaf(g, 5.0f, 5.0f + 1e-7f);
                    bool same = (s_labB[jl] == li);
                    bool isd = (gi == bn + jl);
                    float pc = (same && !isd) ? s : 0.0f;
                    float e  = same ? 0.0f : __expf(s);
                    rps += pc;  rng += e;
                    colPS[nt][b] += pc;  colNG[nt][b] += e;
                }
            }
            rps += __shfl_xor_sync(0xffffffffu, rps, 1);
            rps += __shfl_xor_sync(0xffffffffu, rps, 2);
            rng += __shfl_xor_sync(0xffffffffu, rng, 1);
            rng += __shfl_xor_sync(0xffffffffu, rng, 2);
            if (cpos == 0) {
                atomicAdd(&s_rps[il], rps);
                atomicAdd(&s_rng[il], rng);
            }
        }
    }
    if (!diag) {
        #pragma unroll
        for (int nt = 0; nt < 4; nt++)
            #pragma unroll
            for (int b = 0; b < 2; b++) {
                float p = colPS[nt][b], n = colNG[nt][b];
                p += __shfl_xor_sync(0xffffffffu, p, 4);
                p += __shfl_xor_sync(0xffffffffu, p, 8);
                p += __shfl_xor_sync(0xffffffffu, p, 16);
                n += __shfl_xor_sync(0xffffffffu, n, 4);
                n += __shfl_xor_sync(0xffffffffu, n, 8);
                n += __shfl_xor_sync(0xffffffffu, n, 16);
                if (qid == 0) {
                    int jl = warp_n * 32 + nt * 8 + cpos * 2 + b;
                    atomicAdd(&s_cps[jl], p);
                    atomicAdd(&s_cng[jl], n);
                }
            }
    }
    __syncthreads();
    if (tid < 128) {
        atomicAdd(&g_ps[bm + tid], s_rps[tid]);
        atomicAdd(&g_ng[bm + tid], s_rng[tid]);
        if (!diag) {
            atomicAdd(&g_ps[bn + tid], s_cps[tid]);
            atomicAdd(&g_ng[bn + tid], s_cng[tid]);
        }
    }
}

// ---------------------------------------------------------------------------
// Final: loss_i = -ps/(hist[lab_i]-1+eps) + log(ng+eps); masked mean (loss>0).
// (Global max-shift cancels analytically to ~1e-9 absolute — omitted.)
// ---------------------------------------------------------------------------
__global__ __launch_bounds__(256) void loss_kernel(float* __restrict__ out) {
    __shared__ float hist[NCLS];
    int t = threadIdx.x;
    if (t < NCLS) hist[t] = (float)(g_hist[t] - 1);
    __syncthreads();
    float s = 0.0f, c = 0.0f;
    for (int i = t; i < NN; i += 256) {
        float cnt = hist[g_lab[i]];
        float l = -g_ps[i] / (cnt + 1e-8f) + logf(g_ng[i] + 1e-8f);
        if (l > 0.0f) { s += l; c += 1.0f; }
    }
    #pragma unroll
    for (int o = 16; o > 0; o >>= 1) {
        s += __shfl_down_sync(0xffffffffu, s, o);
        c += __shfl_down_sync(0xffffffffu, c, o);
    }
    __shared__ float ssum[8], scnt[8];
    if ((t & 31) == 0) { ssum[t >> 5] = s; scnt[t >> 5] = c; }
    __syncthreads();
    if (t == 0) {
        float S = 0.0f, C = 0.0f;
        #pragma unroll
        for (int w = 0; w < 8; w++) { S += ssum[w]; C += scnt[w]; }
        out[0] = S / (C + 1e-8f);
    }
}

// ---------------------------------------------------------------------------
extern "C" void kernel_launch(void* const* d_in, const int* in_sizes, int n_in,
                              void* d_out, int out_size) {
    (void)in_sizes; (void)n_in; (void)out_size;
    const float* reps = (const float*)d_in[0];
    const int*   lraw = (const int*)d_in[1];
    float*       out  = (float*)d_out;

    cudaFuncSetAttribute(gram_kernel, cudaFuncAttributeMaxDynamicSharedMemorySize,
                         DSMEM_BYTES);

    init_kernel<<<(NN + 255) / 256, 256>>>();
    label_kernel<<<NN / 256, 256>>>(lraw);
    prep_kernel<<<NN, 128>>>(reps);
    gram_kernel<<<NTRI, 256, DSMEM_BYTES>>>();
    loss_kernel<<<1, 256>>>(out);
}

// round 17
// speedup vs baseline: 3.8153x; 1.0025x over previous
#include <cuda_runtime.h>
#include <cuda_bf16.h>
#include <cstdint>
#include <cmath>

#define NN 8192
#define DD 512
#define NCLS 100
#define NTILE 64                         // 8192/128 tiles per side
#define NTRI (NTILE * (NTILE + 1) / 2)   // 2080 upper-tri tiles

// ---------------------------------------------------------------------------
// Device globals
// ---------------------------------------------------------------------------
static __device__ __nv_bfloat16 g_bf[NN * DD];   // 8 MB normalized bf16 reps
static __device__ int   g_lab[NN];
static __device__ float g_ps[NN];                // sum of pos scores (raw)
static __device__ float g_ng[NN];                // sum of exp(neg scores)

// ---------------------------------------------------------------------------
// Baseline-ISA PTX helpers (no 'a'-features: works at target sm_103)
// ---------------------------------------------------------------------------
__device__ __forceinline__ uint32_t smem_u32(const void* p) {
    uint32_t a;
    asm("{ .reg .u64 t; cvta.to.shared.u64 t, %1; cvt.u32.u64 %0, t; }" : "=r"(a) : "l"(p));
    return a;
}

#define CP_ASYNC16(saddr, gaddr) \
    asm volatile("cp.async.cg.shared.global [%0], [%1], 16;" :: "r"(saddr), "l"(gaddr) : "memory")
#define CP_COMMIT() asm volatile("cp.async.commit_group;" ::: "memory")
#define CP_WAIT0()  asm volatile("cp.async.wait_group 0;" ::: "memory")
#define CP_WAIT1()  asm volatile("cp.async.wait_group 1;" ::: "memory")

#define LDSM4(r0, r1, r2, r3, addr) \
    asm volatile("ldmatrix.sync.aligned.m8n8.x4.shared.b16 {%0,%1,%2,%3}, [%4];" \
                 : "=r"(r0), "=r"(r1), "=r"(r2), "=r"(r3) : "r"(addr))

#define MMA16816(c, a0, a1, a2, a3, b0, b1) \
    asm volatile("mma.sync.aligned.m16n8k16.row.col.f32.bf16.bf16.f32 " \
                 "{%0,%1,%2,%3}, {%4,%5,%6,%7}, {%8,%9}, {%0,%1,%2,%3};" \
                 : "+f"((c)[0]), "+f"((c)[1]), "+f"((c)[2]), "+f"((c)[3]) \
                 : "r"(a0), "r"(a1), "r"(a2), "r"(a3), "r"(b0), "r"(b1))

// ---------------------------------------------------------------------------
// prep: label detect/convert + per-row zeroing + normalize + bf16 convert.
// One block per row (8192 x 128 threads).
// int64 detection: 256 odd 32-bit words of window (i&15) are all zero only
// for int64 labels (int32: P ~ 100^-256).  __syncthreads_or gives block vote.
// ---------------------------------------------------------------------------
__global__ __launch_bounds__(128) void prep_kernel(const float* __restrict__ reps,
                                                   const int* __restrict__ lraw) {
    int i = blockIdx.x;
    int t = threadIdx.x;
    // --- label dtype detection (window of 256 odd words, in-bounds both ways)
    int wbase = 512 * (i & 15);
    int pred = lraw[wbase + 2 * t + 1] | lraw[wbase + 2 * (t + 128) + 1];
    int any = __syncthreads_or(pred);
    if (t == 0) {
        int lab = (any == 0) ? lraw[2 * i] : lraw[i];   // int64 LE low word / int32
        g_lab[i] = lab;
        g_ps[i] = 0.0f;
        g_ng[i] = 0.0f;
    }
    // --- normalize + bf16
    const float4* row = (const float4*)(reps + (size_t)i * DD);
    float4 v = row[t];
    float ss = v.x * v.x + v.y * v.y + v.z * v.z + v.w * v.w;
    #pragma unroll
    for (int o = 16; o > 0; o >>= 1) ss += __shfl_down_sync(0xffffffffu, ss, o);
    __shared__ float ws[4];
    if ((t & 31) == 0) ws[t >> 5] = ss;
    __syncthreads();
    float tot = ws[0] + ws[1] + ws[2] + ws[3];
    float nrm = sqrtf(tot);
    float rn = (nrm > 1e-20f) ? (1.0f / nrm) : 0.0f;
    __nv_bfloat162* bp = (__nv_bfloat162*)(g_bf + (size_t)i * DD + (size_t)t * 4);
    bp[0] = __nv_bfloat162{__float2bfloat16(v.x * rn), __float2bfloat16(v.y * rn)};
    bp[1] = __nv_bfloat162{__float2bfloat16(v.z * rn), __float2bfloat16(v.w * rn)};
}

// ---------------------------------------------------------------------------
// Fused HMMA Gram + contrastive row-sum epilogue.
// 1-D triangular grid (2080 CTAs), 128x128 tile each, pure bf16 single pass.
// 256 threads, 8 warps (2x4), warp tile 64x32; KC=64, 3-stage cp.async.
// R17: per-warp ks ROTATION (r=(wid>>2)*2) — warps sharing an SMSP process
// the chunk's k-slices in opposite phase, so one group's MMA bursts overlap
// the other's LDSM bursts (R16 showed the pipes were serialized: tensor 44%
// + smem 47% ~ sum, caused by barrier-phase-aligned warps).
// ---------------------------------------------------------------------------
#define KC 64
#define ROWB 144                        // 128B data + 16B pad (conflict-free)
#define TILEB (128 * ROWB)              // 18432 B per matrix
#define BUFB (2 * TILEB)                // A, B
#define NSTAGE 3
#define DSMEM_BYTES (NSTAGE * BUFB)     // 110592  (2 CTA/SM)

__global__ __launch_bounds__(256, 2) void gram_kernel() {
    // Triangular index -> (by, bx), bx >= by.
    int tidx = blockIdx.x;
    int by = (int)((2.0 * NTILE + 1.0 - sqrt((2.0 * NTILE + 1.0) * (2.0 * NTILE + 1.0)
                                             - 8.0 * (double)tidx)) * 0.5);
    while ((by + 1) * (2 * NTILE - by) / 2 <= tidx) by++;
    while (by * (2 * NTILE - by + 1) / 2 > tidx) by--;
    int bx = by + (tidx - by * (2 * NTILE - by + 1) / 2);

    extern __shared__ char dsmem[];
    __shared__ float s_rps[128], s_rng[128], s_cps[128], s_cng[128];
    __shared__ int s_labA[128], s_labB[128];

    int tid = threadIdx.x;
    int lane = tid & 31;
    int wid = tid >> 5;          // 0..7
    int warp_m = wid >> 2;       // 0..1
    int warp_n = wid & 3;        // 0..3
    int rot = warp_m * 2;        // per-warp ks rotation (de-phases SMSP pairs)
    bool diag = (bx == by);
    int bm = by << 7, bn = bx << 7;

    uint32_t sbase = smem_u32(dsmem);

    if (tid < 128) {
        s_labA[tid] = g_lab[bm + tid];
        s_labB[tid] = g_lab[bn + tid];
        s_rps[tid] = 0.0f; s_rng[tid] = 0.0f;
        s_cps[tid] = 0.0f; s_cng[tid] = 0.0f;
    }

    // ---- async tile loader (chunk c -> stage s) ----
    auto load_chunk = [&](int c, int s) {
        int k0 = c * KC;
        uint32_t sb = sbase + s * BUFB;
        #pragma unroll
        for (int it = 0; it < 4; it++) {
            int u = tid + it * 256;
            int row = u >> 3;
            int seg = u & 7;
            uint32_t soff = row * ROWB + seg * 16;
            CP_ASYNC16(sb + soff, g_bf + (size_t)(bm + row) * DD + k0 + seg * 8);
            if (!diag)
                CP_ASYNC16(sb + TILEB + soff, g_bf + (size_t)(bn + row) * DD + k0 + seg * 8);
        }
    };

    float acc[4][4][4];
    #pragma unroll
    for (int mt = 0; mt < 4; mt++)
        #pragma unroll
        for (int nt = 0; nt < 4; nt++)
            #pragma unroll
            for (int e = 0; e < 4; e++) acc[mt][nt][e] = 0.0f;

    // Prologue: 2 chunks of runway.
    load_chunk(0, 0); CP_COMMIT();
    load_chunk(1, 1); CP_COMMIT();

    uint32_t boffB = diag ? 0u : (uint32_t)TILEB;   // B aliases A on diag

    // Per-lane fragment addresses.
    int b_nrow = warp_n * 32 + (lane & 7) + ((lane >> 4) << 3);  // +p*16
    int b_koff = ((lane >> 3) & 1) * 8;                          // +kk*16
    int a_row  = warp_m * 64 + (lane & 15);                      // +mt*16
    int a_koff = (lane >> 4) * 8;                                // +kk*16

    const int NCHUNK = DD / KC;  // 8
    int stage = 0;
    for (int c = 0; c < NCHUNK; c++) {
        if (c < NCHUNK - 1) CP_WAIT1(); else CP_WAIT0();
        __syncthreads();

        uint32_t ab = sbase + stage * BUFB;          // A tile
        uint32_t bb = ab + boffB;                    // B tile

        // Head fragment loads for this warp's FIRST k-slice (kk = rot).
        uint32_t af[2][4];
        uint32_t bh[2][8];
        LDSM4(af[0][0], af[0][1], af[0][2], af[0][3],
              ab + (rot * 16 + a_koff) * 2 + a_row * ROWB);
        {
            uint32_t base = bb + (rot * 16 + b_koff) * 2;
            LDSM4(bh[0][0], bh[0][1], bh[0][2], bh[0][3], base + b_nrow * ROWB);
            LDSM4(bh[0][4], bh[0][5], bh[0][6], bh[0][7], base + (b_nrow + 16) * ROWB);
        }
        if (c + 2 < NCHUNK) {
            int ns = stage + 2; if (ns >= NSTAGE) ns -= NSTAGE;
            load_chunk(c + 2, ns);
            CP_COMMIT();
        }

        #pragma unroll
        for (int p = 0; p < 4; p++) {
            int kk = (rot + p) & 3;          // this warp's k-slice order
            int kn = (rot + p + 1) & 3;      // next slice (same chunk buffer)
            int cur = p & 1, nxt = cur ^ 1;
            if (p < 3) {   // prefetch B for next slice
                uint32_t base = bb + (kn * 16 + b_koff) * 2;
                LDSM4(bh[nxt][0], bh[nxt][1], bh[nxt][2], bh[nxt][3], base + b_nrow * ROWB);
                LDSM4(bh[nxt][4], bh[nxt][5], bh[nxt][6], bh[nxt][7], base + (b_nrow + 16) * ROWB);
            }
            uint32_t abase = ab + (kk * 16 + a_koff) * 2;
            #pragma unroll
            for (int mt = 0; mt < 4; mt++) {
                uint32_t* ac = af[mt & 1];
                uint32_t* an = af[(mt & 1) ^ 1];
                if (mt < 3) {         // prefetch A(kk, mt+1)
                    LDSM4(an[0], an[1], an[2], an[3],
                          abase + (a_row + (mt + 1) * 16) * ROWB);
                } else if (p < 3) {   // prefetch A(kn, mt=0) across the slice seam
                    LDSM4(an[0], an[1], an[2], an[3],
                          ab + (kn * 16 + a_koff) * 2 + a_row * ROWB);
                }
                #pragma unroll
                for (int nt = 0; nt < 4; nt++) {
                    int bi = (nt >> 1) * 4 + (nt & 1) * 2;
                    MMA16816(acc[mt][nt], ac[0], ac[1], ac[2], ac[3],
                             bh[cur][bi], bh[cur][bi + 1]);
                }
            }
        }
        stage++; if (stage >= NSTAGE) stage -= NSTAGE;
    }

    // ---------------- fused contrastive epilogue ----------------
    __syncthreads();
    int qid = lane >> 2;        // 0..7
    int cpos = lane & 3;        // 0..3
    float colPS[4][2], colNG[4][2];
    #pragma unroll
    for (int a = 0; a < 4; a++)
        #pragma unroll
        for (int h = 0; h < 2; h++) { colPS[a][h] = 0.0f; colNG[a][h] = 0.0f; }

    #pragma unroll
    for (int mt = 0; mt < 4; mt++) {
        #pragma unroll
        for (int half = 0; half < 2; half++) {
            int il = warp_m * 64 + mt * 16 + qid + half * 8;
            int li = s_labA[il];
            int gi = bm + il;
            float rps = 0.0f, rng = 0.0f;
            #pragma unroll
            for (int nt = 0; nt < 4; nt++) {
                #pragma unroll
                for (int b = 0; b < 2; b++) {
                    int jl = warp_n * 32 + nt * 8 + cpos * 2 + b;
                    float g = acc[mt][nt][half * 2 + b];
                    float s = fmaf(g, 5.0f, 5.0f + 1e-7f);
                    bool same = (s_labB[jl] == li);
                    bool isd = (gi == bn + jl);
                    float pc = (same && !isd) ? s : 0.0f;
                    float e  = same ? 0.0f : __expf(s);
                    rps += pc;  rng += e;
                    colPS[nt][b] += pc;  colNG[nt][b] += e;
                }
            }
            rps += __shfl_xor_sync(0xffffffffu, rps, 1);
            rps += __shfl_xor_sync(0xffffffffu, rps, 2);
            rng += __shfl_xor_sync(0xffffffffu, rng, 1);
            rng += __shfl_xor_sync(0xffffffffu, rng, 2);
            if (cpos == 0) {
                atomicAdd(&s_rps[il], rps);
                atomicAdd(&s_rng[il], rng);
            }
        }
    }
    if (!diag) {
        #pragma unroll
        for (int nt = 0; nt < 4; nt++)
            #pragma unroll
            for (int b = 0; b < 2; b++) {
                float p = colPS[nt][b], n = colNG[nt][b];
                p += __shfl_xor_sync(0xffffffffu, p, 4);
                p += __shfl_xor_sync(0xffffffffu, p, 8);
                p += __shfl_xor_sync(0xffffffffu, p, 16);
                n += __shfl_xor_sync(0xffffffffu, n, 4);
                n += __shfl_xor_sync(0xffffffffu, n, 8);
                n += __shfl_xor_sync(0xffffffffu, n, 16);
                if (qid == 0) {
                    int jl = warp_n * 32 + nt * 8 + cpos * 2 + b;
                    atomicAdd(&s_cps[jl], p);
                    atomicAdd(&s_cng[jl], n);
                }
            }
    }
    __syncthreads();
    if (tid < 128) {
        atomicAdd(&g_ps[bm + tid], s_rps[tid]);
        atomicAdd(&g_ng[bm + tid], s_rng[tid]);
        if (!diag) {
            atomicAdd(&g_ps[bn + tid], s_cps[tid]);
            atomicAdd(&g_ng[bn + tid], s_cng[tid]);
        }
    }
}

// ---------------------------------------------------------------------------
// Final: build class hist from g_lab, then
// loss_i = -ps/(hist[lab_i]-1+eps) + log(ng+eps); masked mean (loss>0).
// ---------------------------------------------------------------------------
__global__ __launch_bounds__(256) void loss_kernel(float* __restrict__ out) {
    __shared__ int ihist[NCLS];
    __shared__ float hist[NCLS];
    int t = threadIdx.x;
    if (t < NCLS) ihist[t] = 0;
    __syncthreads();
    for (int i = t; i < NN; i += 256) atomicAdd(&ihist[g_lab[i]], 1);
    __syncthreads();
    if (t < NCLS) hist[t] = (float)(ihist[t] - 1);
    __syncthreads();
    float s = 0.0f, c = 0.0f;
    for (int i = t; i < NN; i += 256) {
        float cnt = hist[g_lab[i]];
        float l = -g_ps[i] / (cnt + 1e-8f) + logf(g_ng[i] + 1e-8f);
        if (l > 0.0f) { s += l; c += 1.0f; }
    }
    #pragma unroll
    for (int o = 16; o > 0; o >>= 1) {
        s += __shfl_down_sync(0xffffffffu, s, o);
        c += __shfl_down_sync(0xffffffffu, c, o);
    }
    __shared__ float ssum[8], scnt[8];
    if ((t & 31) == 0) { ssum[t >> 5] = s; scnt[t >> 5] = c; }
    __syncthreads();
    if (t == 0) {
        float S = 0.0f, C = 0.0f;
        #pragma unroll
        for (int w = 0; w < 8; w++) { S += ssum[w]; C += scnt[w]; }
        out[0] = S / (C + 1e-8f);
    }
}

// ---------------------------------------------------------------------------
extern "C" void kernel_launch(void* const* d_in, const int* in_sizes, int n_in,
                              void* d_out, int out_size) {
    (void)in_sizes; (void)n_in; (void)out_size;
    const float* reps = (const float*)d_in[0];
    const int*   lraw = (const int*)d_in[1];
    float*       out  = (float*)d_out;

    cudaFuncSetAttribute(gram_kernel, cudaFuncAttributeMaxDynamicSharedMemorySize,
                         DSMEM_BYTES);

    prep_kernel<<<NN, 128>>>(reps, lraw);
    gram_kernel<<<NTRI, 256, DSMEM_BYTES>>>();
    loss_kernel<<<1, 256>>>(out);
}